// round 5
// baseline (speedup 1.0000x reference)
#include <cuda_runtime.h>

#define B_  4
#define N_  8192
#define C_  64
#define M_  2048
#define NW_ 7
#define NSLOT 14
#define QB_ROWS 256
#define KSTEP 64
#define KST 68
#define VST 72
#define SSTAGE (64*KST + 64*VST)   // 8960 words per stage
#define SCALE_LOG2 0.18033688011112042f  // (1/8) * log2(e)

__device__ float g_Q[B_*N_*C_];
__device__ float g_K[B_*N_*C_];
__device__ float g_V[B_*N_*C_];
__device__ float g_O[(long)B_*NSLOT*M_*C_];
__device__ float g_D[B_*NSLOT*M_];

// job table: {qb, chunk, ks0, ks1}, LPT order (heaviest first)
__constant__ int4 c_jobs[12] = {
    {7,0,0,16},{7,1,16,32},{3,0,0,16},
    {6,0,0,14},{6,1,14,28},
    {5,0,0,12},{5,1,12,24},{2,0,0,12},
    {4,0,0,10},{4,1,10,20},
    {1,0,0,8},{0,0,0,4}
};

__device__ __forceinline__ unsigned tf32u(float x) {
    unsigned u; asm("cvt.rna.tf32.f32 %0, %1;" : "=r"(u) : "f"(x)); return u;
}
__device__ __forceinline__ float ex2(float x) {
    float y; asm("ex2.approx.f32 %0, %1;" : "=f"(y) : "f"(x)); return y;
}
__device__ __forceinline__ void mma8(float d[4], const unsigned a[4], unsigned b0, unsigned b1) {
    asm volatile("mma.sync.aligned.m16n8k8.row.col.f32.tf32.tf32.f32 "
        "{%0,%1,%2,%3},{%4,%5,%6,%7},{%8,%9},{%0,%1,%2,%3};"
        : "+f"(d[0]), "+f"(d[1]), "+f"(d[2]), "+f"(d[3])
        : "r"(a[0]), "r"(a[1]), "r"(a[2]), "r"(a[3]), "r"(b0), "r"(b1));
}

// ============================ Kernel 1: QKV (scalar fp32) ============================
__global__ __launch_bounds__(256) void qkv_kernel(const float* __restrict__ x,
                                                  const float* __restrict__ Wq,
                                                  const float* __restrict__ Wk,
                                                  const float* __restrict__ Wv) {
    extern __shared__ float sm1[];
    float* xT = sm1;
    float* Ws = sm1 + 4096;
    const int tid = threadIdx.x;
    const long rowbase = (long)blockIdx.x * 64;

    #pragma unroll
    for (int k = 0; k < 4; k++) {
        int l = tid + k*256;
        int row = l & 63, cg = l >> 6;
        float4 v = *(const float4*)(x + (rowbase + row)*C_ + cg*4);
        xT[(cg*4+0)*64 + row] = v.x;
        xT[(cg*4+1)*64 + row] = v.y;
        xT[(cg*4+2)*64 + row] = v.z;
        xT[(cg*4+3)*64 + row] = v.w;
    }
    {
        const float* Wm[3] = {Wq, Wk, Wv};
        #pragma unroll
        for (int m = 0; m < 3; m++)
            #pragma unroll
            for (int k = 0; k < 4; k++) {
                int l = tid + k*256;
                int cc = l >> 4, jg = l & 15;
                *(float4*)&Ws[cc*192 + m*64 + jg*4] = *(const float4*)(Wm[m] + cc*64 + jg*4);
            }
    }
    __syncthreads();

    const int ty = tid >> 4, tx = tid & 15;
    float acc[3][4][4];
    #pragma unroll
    for (int m = 0; m < 3; m++)
        #pragma unroll
        for (int i = 0; i < 4; i++)
            #pragma unroll
            for (int j = 0; j < 4; j++) acc[m][i][j] = 0.f;

    const float* xp = xT + ty*4;
    #pragma unroll 4
    for (int cc = 0; cc < 64; cc++) {
        float4 xv = *(const float4*)(xp + cc*64);
        float4 w0 = *(const float4*)(Ws + cc*192 +   0 + tx*4);
        float4 w1 = *(const float4*)(Ws + cc*192 +  64 + tx*4);
        float4 w2 = *(const float4*)(Ws + cc*192 + 128 + tx*4);
        float xs[4] = {xv.x, xv.y, xv.z, xv.w};
        float wq[4] = {w0.x, w0.y, w0.z, w0.w};
        float wk[4] = {w1.x, w1.y, w1.z, w1.w};
        float wv[4] = {w2.x, w2.y, w2.z, w2.w};
        #pragma unroll
        for (int i = 0; i < 4; i++)
            #pragma unroll
            for (int j = 0; j < 4; j++) {
                acc[0][i][j] += xs[i]*wq[j];
                acc[1][i][j] += xs[i]*wk[j];
                acc[2][i][j] += xs[i]*wv[j];
            }
    }
    #pragma unroll
    for (int i = 0; i < 4; i++) {
        long rr = (rowbase + ty*4 + i)*C_ + tx*4;
        *(float4*)&g_Q[rr] = make_float4(acc[0][i][0]*SCALE_LOG2, acc[0][i][1]*SCALE_LOG2,
                                         acc[0][i][2]*SCALE_LOG2, acc[0][i][3]*SCALE_LOG2);
        *(float4*)&g_K[rr] = make_float4(acc[1][i][0], acc[1][i][1], acc[1][i][2], acc[1][i][3]);
        *(float4*)&g_V[rr] = make_float4(acc[2][i][0], acc[2][i][1], acc[2][i][2], acc[2][i][3]);
    }
}

// ======= Kernel 2: tf32 flash attention, reg-prefetch + double buffer, 1 sync/step =======
#define LOADKV(KS) do {                                                                 \
    _Pragma("unroll")                                                                   \
    for (int i_ = 0; i_ < 4; i_++) {                                                    \
        int l_ = tid + i_*256;                                                          \
        int slot_ = l_ >> 4, cg_ = (l_ & 15) << 2;                                      \
        int srck_ = (slot_ & ~7) | ((slot_ & 1) << 2) | ((slot_ & 7) >> 1);             \
        kp[i_] = *(const float4*)(Kg + (long)((KS)*KSTEP + srck_)*rs + cg_);            \
        vp[i_] = *(const float4*)(Vg + (long)((KS)*KSTEP + slot_)*rs + cg_);            \
    }                                                                                   \
} while (0)

#define STSKV(STAGE) do {                                                               \
    unsigned* base_ = (unsigned*)smf + (STAGE)*SSTAGE;                                  \
    _Pragma("unroll")                                                                   \
    for (int i_ = 0; i_ < 4; i_++) {                                                    \
        int l_ = tid + i_*256;                                                          \
        int slot_ = l_ >> 4, cg_ = (l_ & 15) << 2;                                      \
        uint4 ku_; ku_.x = tf32u(kp[i_].x); ku_.y = tf32u(kp[i_].y);                    \
        ku_.z = tf32u(kp[i_].z); ku_.w = tf32u(kp[i_].w);                               \
        *(uint4*)(base_ + slot_*KST + cg_) = ku_;                                       \
        uint4 vu_; vu_.x = tf32u(vp[i_].x); vu_.y = tf32u(vp[i_].y);                    \
        vu_.z = tf32u(vp[i_].z); vu_.w = tf32u(vp[i_].w);                               \
        *(uint4*)(base_ + 64*KST + slot_*VST + cg_) = vu_;                              \
    }                                                                                   \
} while (0)

__global__ __launch_bounds__(256, 1) void attn_kernel() {
    extern __shared__ float smf[];
    const int tid  = threadIdx.x;
    const int wid  = tid >> 5, lane = tid & 31;
    const int g    = lane >> 2, t4 = lane & 3;
    const int blk  = blockIdx.x;
    const int4 jb  = c_jobs[blk / 28];
    const int w    = blk % 28;
    const int b    = w / NW_, wi = w % NW_;
    const int qb   = jb.x, chunk = jb.y, ks0 = jb.z, ks1 = jb.w;

    int base, r;
    if      (wi < 4) { base = wi*2048;     r = 1; }
    else if (wi < 6) { base = (wi-4)*4096; r = 2; }
    else             { base = 0;           r = 4; }

    const float* Qg = g_Q + ((long)b*N_ + base)*C_;
    const float* Kg = g_K + ((long)b*N_ + base)*C_;
    const float* Vg = g_V + ((long)b*N_ + base)*C_;
    const int rs = r * C_;

    // ---- Q fragments (registers, whole kernel) ----
    const int row0 = qb*QB_ROWS + 32*wid;
    unsigned qa[2][8][4];
    #pragma unroll
    for (int mt = 0; mt < 2; mt++) {
        const float* q0 = Qg + (long)(row0 + 16*mt + g)*rs;
        const float* q1 = q0 + (long)8*rs;
        #pragma unroll
        for (int s = 0; s < 8; s++) {
            qa[mt][s][0] = tf32u(q0[8*s + t4]);
            qa[mt][s][1] = tf32u(q1[8*s + t4]);
            qa[mt][s][2] = tf32u(q0[8*s + t4 + 4]);
            qa[mt][s][3] = tf32u(q1[8*s + t4 + 4]);
        }
    }

    float oacc[2][8][4];
    float mrow[2][2], lrow[2][2];
    #pragma unroll
    for (int mt = 0; mt < 2; mt++) {
        mrow[mt][0] = mrow[mt][1] = -1e30f;
        lrow[mt][0] = lrow[mt][1] = 0.f;
        #pragma unroll
        for (int j = 0; j < 8; j++)
            #pragma unroll
            for (int q = 0; q < 4; q++) oacc[mt][j][q] = 0.f;
    }

    float4 kp[4], vp[4];
    LOADKV(ks0);
    STSKV(0);
    __syncthreads();

    for (int ks = ks0; ks < ks1; ks++) {
        const int cur = (ks - ks0) & 1;
        const bool more = (ks + 1 < ks1);
        if (more) LOADKV(ks + 1);          // latency hidden behind compute

        const unsigned* Ks = (const unsigned*)smf + (size_t)cur * SSTAGE;
        const unsigned* Vs = Ks + 64*KST;

        // ---- S = Q K^T ----
        float sacc[2][8][4];
        #pragma unroll
        for (int mt = 0; mt < 2; mt++)
            #pragma unroll
            for (int j = 0; j < 8; j++)
                #pragma unroll
                for (int q = 0; q < 4; q++) sacc[mt][j][q] = 0.f;

        #pragma unroll
        for (int s = 0; s < 8; s++) {
            #pragma unroll
            for (int j = 0; j < 8; j++) {
                unsigned b0 = Ks[(8*j + g)*KST + 8*s + t4];
                unsigned b1 = Ks[(8*j + g)*KST + 8*s + t4 + 4];
                mma8(sacc[0][j], qa[0][s], b0, b1);
                mma8(sacc[1][j], qa[1][s], b0, b1);
            }
        }

        // ---- causal mask ----
        if (ks >= 4*qb) {
            #pragma unroll
            for (int mt = 0; mt < 2; mt++) {
                int r0_ = row0 + 16*mt + g, r1_ = r0_ + 8;
                #pragma unroll
                for (int j = 0; j < 8; j++) {
                    int k0 = ks*KSTEP + 8*j + t4, k1 = k0 + 4;
                    if (k0 > r0_) sacc[mt][j][0] = -1e30f;
                    if (k1 > r0_) sacc[mt][j][1] = -1e30f;
                    if (k0 > r1_) sacc[mt][j][2] = -1e30f;
                    if (k1 > r1_) sacc[mt][j][3] = -1e30f;
                }
            }
        }

        // ---- online softmax (log2 domain) ----
        #pragma unroll
        for (int mt = 0; mt < 2; mt++) {
            float rm0 = -1e30f, rm1 = -1e30f;
            #pragma unroll
            for (int j = 0; j < 8; j++) {
                rm0 = fmaxf(rm0, fmaxf(sacc[mt][j][0], sacc[mt][j][1]));
                rm1 = fmaxf(rm1, fmaxf(sacc[mt][j][2], sacc[mt][j][3]));
            }
            rm0 = fmaxf(rm0, __shfl_xor_sync(0xffffffffu, rm0, 1));
            rm0 = fmaxf(rm0, __shfl_xor_sync(0xffffffffu, rm0, 2));
            rm1 = fmaxf(rm1, __shfl_xor_sync(0xffffffffu, rm1, 1));
            rm1 = fmaxf(rm1, __shfl_xor_sync(0xffffffffu, rm1, 2));
            float mn0 = fmaxf(mrow[mt][0], rm0), mn1 = fmaxf(mrow[mt][1], rm1);
            float c0 = ex2(mrow[mt][0] - mn0),   c1 = ex2(mrow[mt][1] - mn1);
            mrow[mt][0] = mn0; mrow[mt][1] = mn1;
            float rs0 = 0.f, rs1 = 0.f;
            #pragma unroll
            for (int j = 0; j < 8; j++) {
                float p0 = ex2(sacc[mt][j][0] - mn0); rs0 += p0; sacc[mt][j][0] = p0;
                float p1 = ex2(sacc[mt][j][1] - mn0); rs0 += p1; sacc[mt][j][1] = p1;
                float p2 = ex2(sacc[mt][j][2] - mn1); rs1 += p2; sacc[mt][j][2] = p2;
                float p3 = ex2(sacc[mt][j][3] - mn1); rs1 += p3; sacc[mt][j][3] = p3;
            }
            rs0 += __shfl_xor_sync(0xffffffffu, rs0, 1);
            rs0 += __shfl_xor_sync(0xffffffffu, rs0, 2);
            rs1 += __shfl_xor_sync(0xffffffffu, rs1, 1);
            rs1 += __shfl_xor_sync(0xffffffffu, rs1, 2);
            lrow[mt][0] = lrow[mt][0]*c0 + rs0;
            lrow[mt][1] = lrow[mt][1]*c1 + rs1;
            #pragma unroll
            for (int jv = 0; jv < 8; jv++) {
                oacc[mt][jv][0] *= c0; oacc[mt][jv][1] *= c0;
                oacc[mt][jv][2] *= c1; oacc[mt][jv][3] *= c1;
            }
        }

        // ---- O += P V ----
        #pragma unroll
        for (int s2 = 0; s2 < 8; s2++) {
            unsigned pa0[4] = { tf32u(sacc[0][s2][0]), tf32u(sacc[0][s2][2]),
                                tf32u(sacc[0][s2][1]), tf32u(sacc[0][s2][3]) };
            unsigned pa1[4] = { tf32u(sacc[1][s2][0]), tf32u(sacc[1][s2][2]),
                                tf32u(sacc[1][s2][1]), tf32u(sacc[1][s2][3]) };
            #pragma unroll
            for (int jv = 0; jv < 8; jv++) {
                unsigned b0 = Vs[(8*s2 + t4)*VST + 8*jv + g];
                unsigned b1 = Vs[(8*s2 + t4 + 4)*VST + 8*jv + g];
                mma8(oacc[0][jv], pa0, b0, b1);
                mma8(oacc[1][jv], pa1, b0, b1);
            }
        }

        if (more) STSKV(cur ^ 1);          // write other stage; no barrier needed before
        __syncthreads();                   // single barrier per step
    }

    // ---- epilogue ----
    const long slot = (long)b*NSLOT + wi + 7*chunk;
    float* Og = g_O + slot*M_*C_;
    float* Dg = g_D + slot*M_;
    #pragma unroll
    for (int mt = 0; mt < 2; mt++) {
        int r0_ = row0 + 16*mt + g, r1_ = r0_ + 8;
        float i0 = 1.0f / lrow[mt][0], i1 = 1.0f / lrow[mt][1];
        #pragma unroll
        for (int jv = 0; jv < 8; jv++) {
            *(float2*)&Og[(long)r0_*C_ + 8*jv + 2*t4] =
                make_float2(oacc[mt][jv][0]*i0, oacc[mt][jv][1]*i0);
            *(float2*)&Og[(long)r1_*C_ + 8*jv + 2*t4] =
                make_float2(oacc[mt][jv][2]*i1, oacc[mt][jv][3]*i1);
        }
        if (t4 == 0) {
            Dg[r0_] = lrow[mt][0] * ex2(mrow[mt][0]);
            Dg[r1_] = lrow[mt][1] * ex2(mrow[mt][1]);
        }
    }
}

// ============================ Kernel 3: mix ============================
__global__ __launch_bounds__(256) void mix_kernel(float* __restrict__ out) {
    const int tid = threadIdx.x;
    const int c = tid & 63;
    const int gp = blockIdx.x*4 + (tid >> 6);
    const int b = gp >> 13;
    const int p = gp & (N_-1);

    float dsum = 0.f, num = 0.f;
    #define ACC1(SLOT, ROW) do {                               \
        long i_ = ((long)b*NSLOT + (SLOT))*M_ + (ROW);         \
        float d_ = g_D[i_];                                    \
        dsum += d_;                                            \
        num  += d_ * g_O[i_*C_ + c];                           \
    } while (0)

    int w0 = p >> 11, r0 = p & 2047;
    ACC1(w0, r0);
    if ((r0 >> 8) >= 4) ACC1(w0 + 7, r0);
    if ((p & 1) == 0) {
        int w1 = 4 + (p >> 12), r1 = (p & 4095) >> 1;
        ACC1(w1, r1);
        if ((r1 >> 8) >= 4) ACC1(w1 + 7, r1);
    }
    if ((p & 3) == 0) {
        int r2 = p >> 2;
        ACC1(6, r2);
        if ((r2 >> 8) >= 4) ACC1(13, r2);
    }
    out[((long)b*N_ + p)*C_ + c] = num / dsum;
    #undef ACC1
}

// =======================================================================
extern "C" void kernel_launch(void* const* d_in, const int* in_sizes, int n_in,
                              void* d_out, int out_size) {
    (void)in_sizes; (void)n_in; (void)out_size;
    const float* x  = (const float*)d_in[0];
    const float* Wq = (const float*)d_in[1];
    const float* Wk = (const float*)d_in[2];
    const float* Wv = (const float*)d_in[3];
    float* out = (float*)d_out;

    const int smem1 = (64*64 + 64*192) * 4;
    const int smem2 = 2 * SSTAGE * 4;   // 71680 B
    cudaFuncSetAttribute(qkv_kernel,  cudaFuncAttributeMaxDynamicSharedMemorySize, smem1);
    cudaFuncSetAttribute(attn_kernel, cudaFuncAttributeMaxDynamicSharedMemorySize, smem2);

    qkv_kernel<<<(B_*N_)/64, 256, smem1>>>(x, Wq, Wk, Wv);
    attn_kernel<<<12*28, 256, smem2>>>();
    mix_kernel<<<(B_*N_)/4, 256>>>(out);
}

// round 6
// speedup vs baseline: 1.0823x; 1.0823x over previous
#include <cuda_runtime.h>

#define B_  4
#define N_  8192
#define C_  64
#define M_  2048
#define NW_ 7
#define QB_ROWS 256
#define NQB 8
#define KSTEP 64
#define KST 68
#define VST 72
#define SCALE_LOG2 0.18033688011112042f  // (1/8) * log2(e)

__device__ float g_Q[B_*N_*C_];
__device__ float g_K[B_*N_*C_];
__device__ float g_V[B_*N_*C_];
__device__ float g_O[(long)B_*NW_*M_*C_];
__device__ float g_D[B_*NW_*M_];

__device__ __forceinline__ unsigned tf32u(float x) {
    unsigned u; asm("cvt.rna.tf32.f32 %0, %1;" : "=r"(u) : "f"(x)); return u;
}
__device__ __forceinline__ float ex2(float x) {
    float y; asm("ex2.approx.f32 %0, %1;" : "=f"(y) : "f"(x)); return y;
}
__device__ __forceinline__ void mma8(float d[4], const unsigned a[4], unsigned b0, unsigned b1) {
    asm volatile("mma.sync.aligned.m16n8k8.row.col.f32.tf32.tf32.f32 "
        "{%0,%1,%2,%3},{%4,%5,%6,%7},{%8,%9},{%0,%1,%2,%3};"
        : "+f"(d[0]), "+f"(d[1]), "+f"(d[2]), "+f"(d[3])
        : "r"(a[0]), "r"(a[1]), "r"(a[2]), "r"(a[3]), "r"(b0), "r"(b1));
}

// ============================ Kernel 1: QKV (scalar fp32) ============================
__global__ __launch_bounds__(256) void qkv_kernel(const float* __restrict__ x,
                                                  const float* __restrict__ Wq,
                                                  const float* __restrict__ Wk,
                                                  const float* __restrict__ Wv) {
    extern __shared__ float sm1[];
    float* xT = sm1;
    float* Ws = sm1 + 4096;
    const int tid = threadIdx.x;
    const long rowbase = (long)blockIdx.x * 64;

    #pragma unroll
    for (int k = 0; k < 4; k++) {
        int l = tid + k*256;
        int row = l & 63, cg = l >> 6;
        float4 v = *(const float4*)(x + (rowbase + row)*C_ + cg*4);
        xT[(cg*4+0)*64 + row] = v.x;
        xT[(cg*4+1)*64 + row] = v.y;
        xT[(cg*4+2)*64 + row] = v.z;
        xT[(cg*4+3)*64 + row] = v.w;
    }
    {
        const float* Wm[3] = {Wq, Wk, Wv};
        #pragma unroll
        for (int m = 0; m < 3; m++)
            #pragma unroll
            for (int k = 0; k < 4; k++) {
                int l = tid + k*256;
                int cc = l >> 4, jg = l & 15;
                *(float4*)&Ws[cc*192 + m*64 + jg*4] = *(const float4*)(Wm[m] + cc*64 + jg*4);
            }
    }
    __syncthreads();

    const int ty = tid >> 4, tx = tid & 15;
    float acc[3][4][4];
    #pragma unroll
    for (int m = 0; m < 3; m++)
        #pragma unroll
        for (int i = 0; i < 4; i++)
            #pragma unroll
            for (int j = 0; j < 4; j++) acc[m][i][j] = 0.f;

    const float* xp = xT + ty*4;
    #pragma unroll 4
    for (int cc = 0; cc < 64; cc++) {
        float4 xv = *(const float4*)(xp + cc*64);
        float4 w0 = *(const float4*)(Ws + cc*192 +   0 + tx*4);
        float4 w1 = *(const float4*)(Ws + cc*192 +  64 + tx*4);
        float4 w2 = *(const float4*)(Ws + cc*192 + 128 + tx*4);
        float xs[4] = {xv.x, xv.y, xv.z, xv.w};
        float wq[4] = {w0.x, w0.y, w0.z, w0.w};
        float wk[4] = {w1.x, w1.y, w1.z, w1.w};
        float wv[4] = {w2.x, w2.y, w2.z, w2.w};
        #pragma unroll
        for (int i = 0; i < 4; i++)
            #pragma unroll
            for (int j = 0; j < 4; j++) {
                acc[0][i][j] += xs[i]*wq[j];
                acc[1][i][j] += xs[i]*wk[j];
                acc[2][i][j] += xs[i]*wv[j];
            }
    }
    #pragma unroll
    for (int i = 0; i < 4; i++) {
        long rr = (rowbase + ty*4 + i)*C_ + tx*4;
        *(float4*)&g_Q[rr] = make_float4(acc[0][i][0]*SCALE_LOG2, acc[0][i][1]*SCALE_LOG2,
                                         acc[0][i][2]*SCALE_LOG2, acc[0][i][3]*SCALE_LOG2);
        *(float4*)&g_K[rr] = make_float4(acc[1][i][0], acc[1][i][1], acc[1][i][2], acc[1][i][3]);
        *(float4*)&g_V[rr] = make_float4(acc[2][i][0], acc[2][i][1], acc[2][i][2], acc[2][i][3]);
    }
}

// ====== Kernel 2: tf32 flash attention — 512 threads, 16 warps, 16 q-rows/warp ======
__global__ __launch_bounds__(512, 1) void attn_kernel() {
    extern __shared__ unsigned smu[];
    unsigned* Ks = smu;              // [64][KST]
    unsigned* Vs = smu + 64*KST;     // [64][VST]

    const int tid  = threadIdx.x;
    const int wid  = tid >> 5, lane = tid & 31;
    const int g    = lane >> 2, t4 = lane & 3;
    const int blk  = blockIdx.x;
    const int qb   = (NQB - 1) - blk / (B_*NW_);   // heaviest first (LPT)
    const int w    = blk % (B_*NW_);
    const int b    = w / NW_, wi = w % NW_;

    int base, r;
    if      (wi < 4) { base = wi*2048;     r = 1; }
    else if (wi < 6) { base = (wi-4)*4096; r = 2; }
    else             { base = 0;           r = 4; }

    const float* Qg = g_Q + ((long)b*N_ + base)*C_;
    const float* Kg = g_K + ((long)b*N_ + base)*C_;
    const float* Vg = g_V + ((long)b*N_ + base)*C_;
    const int rs = r * C_;

    // ---- Q fragments for this warp's 16 rows (registers, whole kernel) ----
    const int row0 = qb*QB_ROWS + 16*wid;
    unsigned qa[8][4];
    {
        const float* q0 = Qg + (long)(row0 + g)*rs;
        const float* q1 = q0 + (long)8*rs;
        #pragma unroll
        for (int s = 0; s < 8; s++) {
            qa[s][0] = tf32u(q0[8*s + t4]);
            qa[s][1] = tf32u(q1[8*s + t4]);
            qa[s][2] = tf32u(q0[8*s + t4 + 4]);
            qa[s][3] = tf32u(q1[8*s + t4 + 4]);
        }
    }

    float oacc[8][4];
    float m0 = -1e30f, m1 = -1e30f, l0 = 0.f, l1 = 0.f;
    #pragma unroll
    for (int j = 0; j < 8; j++)
        #pragma unroll
        for (int q = 0; q < 4; q++) oacc[j][q] = 0.f;

    const int nks = 4*qb + 4;
    for (int ks = 0; ks < nks; ks++) {
        __syncthreads();
        // ---- fill K (rows permuted by kappa within 8-groups) + V, cvt.rna tf32 ----
        #pragma unroll
        for (int i = 0; i < 2; i++) {
            int l = tid + i*512;
            int slot = l >> 4, cg = (l & 15) << 2;
            int srck = (slot & ~7) | ((slot & 1) << 2) | ((slot & 7) >> 1);
            float4 kv = *(const float4*)(Kg + (long)(ks*KSTEP + srck)*rs + cg);
            uint4 ku; ku.x = tf32u(kv.x); ku.y = tf32u(kv.y); ku.z = tf32u(kv.z); ku.w = tf32u(kv.w);
            *(uint4*)&Ks[slot*KST + cg] = ku;
            float4 vv = *(const float4*)(Vg + (long)(ks*KSTEP + slot)*rs + cg);
            uint4 vu; vu.x = tf32u(vv.x); vu.y = tf32u(vv.y); vu.z = tf32u(vv.z); vu.w = tf32u(vv.w);
            *(uint4*)&Vs[slot*VST + cg] = vu;
        }
        __syncthreads();

        // ---- S = Q K^T (16 x 64 per warp) ----
        float sacc[8][4];
        #pragma unroll
        for (int j = 0; j < 8; j++)
            #pragma unroll
            for (int q = 0; q < 4; q++) sacc[j][q] = 0.f;

        #pragma unroll
        for (int s = 0; s < 8; s++) {
            #pragma unroll
            for (int j = 0; j < 8; j++) {
                unsigned b0 = Ks[(8*j + g)*KST + 8*s + t4];
                unsigned b1 = Ks[(8*j + g)*KST + 8*s + t4 + 4];
                mma8(sacc[j], qa[s], b0, b1);
            }
        }

        // ---- causal mask (logical keys: c0->8j+t4, c1->8j+t4+4) ----
        if (ks >= 4*qb) {
            int r0_ = row0 + g, r1_ = r0_ + 8;
            #pragma unroll
            for (int j = 0; j < 8; j++) {
                int k0 = ks*KSTEP + 8*j + t4, k1 = k0 + 4;
                if (k0 > r0_) sacc[j][0] = -1e30f;
                if (k1 > r0_) sacc[j][1] = -1e30f;
                if (k0 > r1_) sacc[j][2] = -1e30f;
                if (k1 > r1_) sacc[j][3] = -1e30f;
            }
        }

        // ---- online softmax (log2 domain) ----
        {
            float rm0 = -1e30f, rm1 = -1e30f;
            #pragma unroll
            for (int j = 0; j < 8; j++) {
                rm0 = fmaxf(rm0, fmaxf(sacc[j][0], sacc[j][1]));
                rm1 = fmaxf(rm1, fmaxf(sacc[j][2], sacc[j][3]));
            }
            rm0 = fmaxf(rm0, __shfl_xor_sync(0xffffffffu, rm0, 1));
            rm0 = fmaxf(rm0, __shfl_xor_sync(0xffffffffu, rm0, 2));
            rm1 = fmaxf(rm1, __shfl_xor_sync(0xffffffffu, rm1, 1));
            rm1 = fmaxf(rm1, __shfl_xor_sync(0xffffffffu, rm1, 2));
            float mn0 = fmaxf(m0, rm0), mn1 = fmaxf(m1, rm1);
            float c0 = ex2(m0 - mn0),   c1 = ex2(m1 - mn1);
            m0 = mn0; m1 = mn1;
            float rs0 = 0.f, rs1 = 0.f;
            #pragma unroll
            for (int j = 0; j < 8; j++) {
                float p0 = ex2(sacc[j][0] - mn0); rs0 += p0; sacc[j][0] = p0;
                float p1 = ex2(sacc[j][1] - mn0); rs0 += p1; sacc[j][1] = p1;
                float p2 = ex2(sacc[j][2] - mn1); rs1 += p2; sacc[j][2] = p2;
                float p3 = ex2(sacc[j][3] - mn1); rs1 += p3; sacc[j][3] = p3;
            }
            rs0 += __shfl_xor_sync(0xffffffffu, rs0, 1);
            rs0 += __shfl_xor_sync(0xffffffffu, rs0, 2);
            rs1 += __shfl_xor_sync(0xffffffffu, rs1, 1);
            rs1 += __shfl_xor_sync(0xffffffffu, rs1, 2);
            l0 = l0*c0 + rs0;
            l1 = l1*c1 + rs1;
            #pragma unroll
            for (int jv = 0; jv < 8; jv++) {
                oacc[jv][0] *= c0; oacc[jv][1] *= c0;
                oacc[jv][2] *= c1; oacc[jv][3] *= c1;
            }
        }

        // ---- O += P V (S C-frags -> A-frags via kappa permutation) ----
        #pragma unroll
        for (int s2 = 0; s2 < 8; s2++) {
            unsigned pa[4] = { tf32u(sacc[s2][0]), tf32u(sacc[s2][2]),
                               tf32u(sacc[s2][1]), tf32u(sacc[s2][3]) };
            #pragma unroll
            for (int jv = 0; jv < 8; jv++) {
                unsigned b0 = Vs[(8*s2 + t4)*VST + 8*jv + g];
                unsigned b1 = Vs[(8*s2 + t4 + 4)*VST + 8*jv + g];
                mma8(oacc[jv], pa, b0, b1);
            }
        }
    }

    // ---- epilogue: normalized O + denominator d = l * 2^m ----
    float* Og = g_O + (long)(b*NW_ + wi)*M_*C_;
    float* Dg = g_D + (long)(b*NW_ + wi)*M_;
    {
        int r0_ = row0 + g, r1_ = r0_ + 8;
        float i0 = 1.0f / l0, i1 = 1.0f / l1;
        #pragma unroll
        for (int jv = 0; jv < 8; jv++) {
            *(float2*)&Og[(long)r0_*C_ + 8*jv + 2*t4] =
                make_float2(oacc[jv][0]*i0, oacc[jv][1]*i0);
            *(float2*)&Og[(long)r1_*C_ + 8*jv + 2*t4] =
                make_float2(oacc[jv][2]*i1, oacc[jv][3]*i1);
        }
        if (t4 == 0) {
            Dg[r0_] = l0 * ex2(m0);
            Dg[r1_] = l1 * ex2(m1);
        }
    }
}

// ============================ Kernel 3: mix ============================
__global__ __launch_bounds__(256) void mix_kernel(float* __restrict__ out) {
    const int tid = threadIdx.x;
    const int c = tid & 63;
    const int gp = blockIdx.x*4 + (tid >> 6);
    const int b = gp >> 13;
    const int p = gp & (N_-1);

    int w0 = p >> 11, r0 = p & 2047;
    long i0 = (long)(b*NW_ + w0)*M_ + r0;
    float d0 = g_D[i0];
    float dsum = d0;
    float num  = d0 * g_O[i0*C_ + c];

    if ((p & 1) == 0) {
        int w1 = 4 + (p >> 12), r1 = (p & 4095) >> 1;
        long i1 = (long)(b*NW_ + w1)*M_ + r1;
        float d1 = g_D[i1];
        dsum += d1;
        num  += d1 * g_O[i1*C_ + c];
    }
    if ((p & 3) == 0) {
        long i2 = (long)(b*NW_ + 6)*M_ + (p >> 2);
        float d2 = g_D[i2];
        dsum += d2;
        num  += d2 * g_O[i2*C_ + c];
    }
    out[((long)b*N_ + p)*C_ + c] = num / dsum;
}

// =======================================================================
extern "C" void kernel_launch(void* const* d_in, const int* in_sizes, int n_in,
                              void* d_out, int out_size) {
    (void)in_sizes; (void)n_in; (void)out_size;
    const float* x  = (const float*)d_in[0];
    const float* Wq = (const float*)d_in[1];
    const float* Wk = (const float*)d_in[2];
    const float* Wv = (const float*)d_in[3];
    float* out = (float*)d_out;

    const int smem1 = (64*64 + 64*192) * 4;
    const int smem2 = (64*KST + 64*VST) * 4;   // 35840 B
    cudaFuncSetAttribute(qkv_kernel,  cudaFuncAttributeMaxDynamicSharedMemorySize, smem1);
    cudaFuncSetAttribute(attn_kernel, cudaFuncAttributeMaxDynamicSharedMemorySize, smem2);

    qkv_kernel<<<(B_*N_)/64, 256, smem1>>>(x, Wq, Wk, Wv);
    attn_kernel<<<NQB * B_ * NW_, 512, smem2>>>();
    mix_kernel<<<(B_*N_)/4, 256>>>(out);
}

// round 7
// speedup vs baseline: 1.1930x; 1.1023x over previous
#include <cuda_runtime.h>

#define B_  4
#define N_  8192
#define C_  64
#define M_  2048
#define NW_ 7
#define QB_ROWS 256
#define NQB 8
#define KST 68
#define VST 72
#define WST 68
#define SCALE_LOG2 0.18033688011112042f  // (1/8) * log2(e)

__device__ float g_Q[B_*N_*C_];
__device__ float g_K[B_*N_*C_];
__device__ float g_V[B_*N_*C_];
__device__ float g_O[(long)B_*NW_*M_*C_];
__device__ float g_D[B_*NW_*M_];

__device__ __forceinline__ unsigned tf32u(float x) {
    unsigned u; asm("cvt.rna.tf32.f32 %0, %1;" : "=r"(u) : "f"(x)); return u;
}
__device__ __forceinline__ float ex2(float x) {
    float y; asm("ex2.approx.f32 %0, %1;" : "=f"(y) : "f"(x)); return y;
}
__device__ __forceinline__ void mma8(float d[4], const unsigned a[4], unsigned b0, unsigned b1) {
    asm volatile("mma.sync.aligned.m16n8k8.row.col.f32.tf32.tf32.f32 "
        "{%0,%1,%2,%3},{%4,%5,%6,%7},{%8,%9},{%0,%1,%2,%3};"
        : "+f"(d[0]), "+f"(d[1]), "+f"(d[2]), "+f"(d[3])
        : "r"(a[0]), "r"(a[1]), "r"(a[2]), "r"(a[3]), "r"(b0), "r"(b1));
}

// ================= Kernel 1: QKV projection, tf32 tensor cores =================
// CTA: 128 rows of x; 8 warps x 16 rows; each warp computes all 192 out cols.
// smem: Wt[192][WST] = W^T (tf32 bits), conflict-free B-frag reads.
__global__ __launch_bounds__(256) void qkv_kernel(const float* __restrict__ x,
                                                  const float* __restrict__ Wq,
                                                  const float* __restrict__ Wk,
                                                  const float* __restrict__ Wv) {
    extern __shared__ unsigned smw[];   // Wt[192*WST]
    const int tid = threadIdx.x;
    const int wid = tid >> 5, lane = tid & 31;
    const int g = lane >> 2, t4 = lane & 3;

    // stage W^T: Wt[n][k] = W[k][n]  (coalesced reads of W rows)
    const float* Wm[3] = {Wq, Wk, Wv};
    for (int idx = tid; idx < 192*64; idx += 256) {
        int k = idx / 192, nn = idx % 192;
        float v = Wm[nn >> 6][k*64 + (nn & 63)];
        smw[nn*WST + k] = tf32u(v);
    }
    __syncthreads();

    // A-fragments from gmem: 16 rows per warp
    const long row0 = (long)blockIdx.x*128 + 16*wid;
    const float* x0 = x + (row0 + g)*C_;
    const float* x1 = x0 + 8*C_;
    unsigned a[8][4];
    #pragma unroll
    for (int s = 0; s < 8; s++) {
        a[s][0] = tf32u(x0[8*s + t4]);
        a[s][1] = tf32u(x1[8*s + t4]);
        a[s][2] = tf32u(x0[8*s + t4 + 4]);
        a[s][3] = tf32u(x1[8*s + t4 + 4]);
    }

    float acc[24][4];
    #pragma unroll
    for (int j = 0; j < 24; j++)
        #pragma unroll
        for (int q = 0; q < 4; q++) acc[j][q] = 0.f;

    #pragma unroll
    for (int s = 0; s < 8; s++) {
        #pragma unroll
        for (int j = 0; j < 24; j++) {
            unsigned b0 = smw[(8*j + g)*WST + 8*s + t4];
            unsigned b1 = smw[(8*j + g)*WST + 8*s + t4 + 4];
            mma8(acc[j], a[s], b0, b1);
        }
    }

    // store: j 0-7 -> Q (scaled), 8-15 -> K, 16-23 -> V
    const long r0 = row0 + g, r1 = r0 + 8;
    #pragma unroll
    for (int j = 0; j < 24; j++) {
        int col = ((j & 7) << 3) + 2*t4;
        float* dst = (j < 8) ? g_Q : (j < 16) ? g_K : g_V;
        float sc = (j < 8) ? SCALE_LOG2 : 1.0f;
        *(float2*)&dst[r0*C_ + col] = make_float2(acc[j][0]*sc, acc[j][1]*sc);
        *(float2*)&dst[r1*C_ + col] = make_float2(acc[j][2]*sc, acc[j][3]*sc);
    }
}

// ==== Kernel 2: tf32 flash attention — 128-key steps, two 64-key sub-passes ====
__global__ __launch_bounds__(256, 1) void attn_kernel() {
    extern __shared__ unsigned smu[];
    unsigned* Ks = smu;               // [128][KST]
    unsigned* Vs = smu + 128*KST;     // [128][VST]

    const int tid  = threadIdx.x;
    const int wid  = tid >> 5, lane = tid & 31;
    const int g    = lane >> 2, t4 = lane & 3;
    const int blk  = blockIdx.x;
    const int qb   = (NQB - 1) - blk / (B_*NW_);   // heaviest first (LPT)
    const int w    = blk % (B_*NW_);
    const int b    = w / NW_, wi = w % NW_;

    int base, r;
    if      (wi < 4) { base = wi*2048;     r = 1; }
    else if (wi < 6) { base = (wi-4)*4096; r = 2; }
    else             { base = 0;           r = 4; }

    const float* Qg = g_Q + ((long)b*N_ + base)*C_;
    const float* Kg = g_K + ((long)b*N_ + base)*C_;
    const float* Vg = g_V + ((long)b*N_ + base)*C_;
    const int rs = r * C_;

    // Q fragments (registers, whole kernel): 32 rows/warp, 2 m-tiles
    const int row0 = qb*QB_ROWS + 32*wid;
    unsigned qa[2][8][4];
    #pragma unroll
    for (int mt = 0; mt < 2; mt++) {
        const float* q0 = Qg + (long)(row0 + 16*mt + g)*rs;
        const float* q1 = q0 + (long)8*rs;
        #pragma unroll
        for (int s = 0; s < 8; s++) {
            qa[mt][s][0] = tf32u(q0[8*s + t4]);
            qa[mt][s][1] = tf32u(q1[8*s + t4]);
            qa[mt][s][2] = tf32u(q0[8*s + t4 + 4]);
            qa[mt][s][3] = tf32u(q1[8*s + t4 + 4]);
        }
    }

    float oacc[2][8][4];
    float mrow[2][2], lrow[2][2];
    #pragma unroll
    for (int mt = 0; mt < 2; mt++) {
        mrow[mt][0] = mrow[mt][1] = -1e30f;
        lrow[mt][0] = lrow[mt][1] = 0.f;
        #pragma unroll
        for (int j = 0; j < 8; j++)
            #pragma unroll
            for (int q = 0; q < 4; q++) oacc[mt][j][q] = 0.f;
    }

    const int nks = 2*qb + 2;          // 128-key steps
    for (int ks = 0; ks < nks; ks++) {
        __syncthreads();
        // fill 128 K rows (kappa-permuted within 8-groups) + 128 V rows
        #pragma unroll
        for (int i = 0; i < 8; i++) {
            int l = tid + i*256;
            int slot = l >> 4, cg = (l & 15) << 2;
            int srck = (slot & ~7) | ((slot & 1) << 2) | ((slot & 7) >> 1);
            float4 kv = *(const float4*)(Kg + (long)(ks*128 + srck)*rs + cg);
            uint4 ku; ku.x = tf32u(kv.x); ku.y = tf32u(kv.y); ku.z = tf32u(kv.z); ku.w = tf32u(kv.w);
            *(uint4*)&Ks[slot*KST + cg] = ku;
            float4 vv = *(const float4*)(Vg + (long)(ks*128 + slot)*rs + cg);
            uint4 vu; vu.x = tf32u(vv.x); vu.y = tf32u(vv.y); vu.z = tf32u(vv.z); vu.w = tf32u(vv.w);
            *(uint4*)&Vs[slot*VST + cg] = vu;
        }
        __syncthreads();

        #pragma unroll
        for (int half = 0; half < 2; half++) {
            const unsigned* Ksh = Ks + (half*64)*KST;
            const unsigned* Vsh = Vs + (half*64)*VST;
            const int kbase = ks*128 + half*64;

            // ---- S = Q K^T (32 x 64 per warp) ----
            float sacc[2][8][4];
            #pragma unroll
            for (int mt = 0; mt < 2; mt++)
                #pragma unroll
                for (int j = 0; j < 8; j++)
                    #pragma unroll
                    for (int q = 0; q < 4; q++) sacc[mt][j][q] = 0.f;

            #pragma unroll
            for (int s = 0; s < 8; s++) {
                #pragma unroll
                for (int j = 0; j < 8; j++) {
                    unsigned b0 = Ksh[(8*j + g)*KST + 8*s + t4];
                    unsigned b1 = Ksh[(8*j + g)*KST + 8*s + t4 + 4];
                    mma8(sacc[0][j], qa[0][s], b0, b1);
                    mma8(sacc[1][j], qa[1][s], b0, b1);
                }
            }

            // ---- causal mask (diagonal 256-key region) ----
            if (ks >= 2*qb) {
                #pragma unroll
                for (int mt = 0; mt < 2; mt++) {
                    int r0_ = row0 + 16*mt + g, r1_ = r0_ + 8;
                    #pragma unroll
                    for (int j = 0; j < 8; j++) {
                        int k0 = kbase + 8*j + t4, k1 = k0 + 4;
                        if (k0 > r0_) sacc[mt][j][0] = -1e30f;
                        if (k1 > r0_) sacc[mt][j][1] = -1e30f;
                        if (k0 > r1_) sacc[mt][j][2] = -1e30f;
                        if (k1 > r1_) sacc[mt][j][3] = -1e30f;
                    }
                }
            }

            // ---- online softmax (log2 domain) ----
            #pragma unroll
            for (int mt = 0; mt < 2; mt++) {
                float rm0 = -1e30f, rm1 = -1e30f;
                #pragma unroll
                for (int j = 0; j < 8; j++) {
                    rm0 = fmaxf(rm0, fmaxf(sacc[mt][j][0], sacc[mt][j][1]));
                    rm1 = fmaxf(rm1, fmaxf(sacc[mt][j][2], sacc[mt][j][3]));
                }
                rm0 = fmaxf(rm0, __shfl_xor_sync(0xffffffffu, rm0, 1));
                rm0 = fmaxf(rm0, __shfl_xor_sync(0xffffffffu, rm0, 2));
                rm1 = fmaxf(rm1, __shfl_xor_sync(0xffffffffu, rm1, 1));
                rm1 = fmaxf(rm1, __shfl_xor_sync(0xffffffffu, rm1, 2));
                float mn0 = fmaxf(mrow[mt][0], rm0), mn1 = fmaxf(mrow[mt][1], rm1);
                float c0 = ex2(mrow[mt][0] - mn0),   c1 = ex2(mrow[mt][1] - mn1);
                mrow[mt][0] = mn0; mrow[mt][1] = mn1;
                float rs0 = 0.f, rs1 = 0.f;
                #pragma unroll
                for (int j = 0; j < 8; j++) {
                    float p0 = ex2(sacc[mt][j][0] - mn0); rs0 += p0; sacc[mt][j][0] = p0;
                    float p1 = ex2(sacc[mt][j][1] - mn0); rs0 += p1; sacc[mt][j][1] = p1;
                    float p2 = ex2(sacc[mt][j][2] - mn1); rs1 += p2; sacc[mt][j][2] = p2;
                    float p3 = ex2(sacc[mt][j][3] - mn1); rs1 += p3; sacc[mt][j][3] = p3;
                }
                rs0 += __shfl_xor_sync(0xffffffffu, rs0, 1);
                rs0 += __shfl_xor_sync(0xffffffffu, rs0, 2);
                rs1 += __shfl_xor_sync(0xffffffffu, rs1, 1);
                rs1 += __shfl_xor_sync(0xffffffffu, rs1, 2);
                lrow[mt][0] = lrow[mt][0]*c0 + rs0;
                lrow[mt][1] = lrow[mt][1]*c1 + rs1;
                #pragma unroll
                for (int jv = 0; jv < 8; jv++) {
                    oacc[mt][jv][0] *= c0; oacc[mt][jv][1] *= c0;
                    oacc[mt][jv][2] *= c1; oacc[mt][jv][3] *= c1;
                }
            }

            // ---- O += P V (S C-frags -> A-frags via kappa) ----
            #pragma unroll
            for (int s2 = 0; s2 < 8; s2++) {
                unsigned pa0[4] = { tf32u(sacc[0][s2][0]), tf32u(sacc[0][s2][2]),
                                    tf32u(sacc[0][s2][1]), tf32u(sacc[0][s2][3]) };
                unsigned pa1[4] = { tf32u(sacc[1][s2][0]), tf32u(sacc[1][s2][2]),
                                    tf32u(sacc[1][s2][1]), tf32u(sacc[1][s2][3]) };
                #pragma unroll
                for (int jv = 0; jv < 8; jv++) {
                    unsigned b0 = Vsh[(8*s2 + t4)*VST + 8*jv + g];
                    unsigned b1 = Vsh[(8*s2 + t4 + 4)*VST + 8*jv + g];
                    mma8(oacc[0][jv], pa0, b0, b1);
                    mma8(oacc[1][jv], pa1, b0, b1);
                }
            }
        }
    }

    // ---- epilogue: normalized O + denominator d = l * 2^m ----
    float* Og = g_O + (long)(b*NW_ + wi)*M_*C_;
    float* Dg = g_D + (long)(b*NW_ + wi)*M_;
    #pragma unroll
    for (int mt = 0; mt < 2; mt++) {
        int r0_ = row0 + 16*mt + g, r1_ = r0_ + 8;
        float i0 = 1.0f / lrow[mt][0], i1 = 1.0f / lrow[mt][1];
        #pragma unroll
        for (int jv = 0; jv < 8; jv++) {
            *(float2*)&Og[(long)r0_*C_ + 8*jv + 2*t4] =
                make_float2(oacc[mt][jv][0]*i0, oacc[mt][jv][1]*i0);
            *(float2*)&Og[(long)r1_*C_ + 8*jv + 2*t4] =
                make_float2(oacc[mt][jv][2]*i1, oacc[mt][jv][3]*i1);
        }
        if (t4 == 0) {
            Dg[r0_] = lrow[mt][0] * ex2(mrow[mt][0]);
            Dg[r1_] = lrow[mt][1] * ex2(mrow[mt][1]);
        }
    }
}

// ============================ Kernel 3: mix ============================
__global__ __launch_bounds__(256) void mix_kernel(float* __restrict__ out) {
    const int tid = threadIdx.x;
    const int c = tid & 63;
    const int gp = blockIdx.x*4 + (tid >> 6);
    const int b = gp >> 13;
    const int p = gp & (N_-1);

    int w0 = p >> 11, r0 = p & 2047;
    long i0 = (long)(b*NW_ + w0)*M_ + r0;
    float d0 = g_D[i0];
    float dsum = d0;
    float num  = d0 * g_O[i0*C_ + c];

    if ((p & 1) == 0) {
        int w1 = 4 + (p >> 12), r1 = (p & 4095) >> 1;
        long i1 = (long)(b*NW_ + w1)*M_ + r1;
        float d1 = g_D[i1];
        dsum += d1;
        num  += d1 * g_O[i1*C_ + c];
    }
    if ((p & 3) == 0) {
        long i2 = (long)(b*NW_ + 6)*M_ + (p >> 2);
        float d2 = g_D[i2];
        dsum += d2;
        num  += d2 * g_O[i2*C_ + c];
    }
    out[((long)b*N_ + p)*C_ + c] = num / dsum;
}

// =======================================================================
extern "C" void kernel_launch(void* const* d_in, const int* in_sizes, int n_in,
                              void* d_out, int out_size) {
    (void)in_sizes; (void)n_in; (void)out_size;
    const float* x  = (const float*)d_in[0];
    const float* Wq = (const float*)d_in[1];
    const float* Wk = (const float*)d_in[2];
    const float* Wv = (const float*)d_in[3];
    float* out = (float*)d_out;

    const int smem1 = 192*WST*4;                    // 52224 B
    const int smem2 = (128*KST + 128*VST) * 4;      // 71680 B
    cudaFuncSetAttribute(qkv_kernel,  cudaFuncAttributeMaxDynamicSharedMemorySize, smem1);
    cudaFuncSetAttribute(attn_kernel, cudaFuncAttributeMaxDynamicSharedMemorySize, smem2);

    qkv_kernel<<<(B_*N_)/128, 256, smem1>>>(x, Wq, Wk, Wv);
    attn_kernel<<<NQB * B_ * NW_, 256, smem2>>>();
    mix_kernel<<<(B_*N_)/4, 256>>>(out);
}

// round 8
// speedup vs baseline: 1.2119x; 1.0158x over previous
#include <cuda_runtime.h>

#define B_  4
#define N_  8192
#define C_  64
#define M_  2048
#define NW_ 7
#define QB_ROWS 256
#define NQB 8
#define KST 68
#define VST 72
#define WST 68
#define SCALE_LOG2 0.18033688011112042f  // (1/8) * log2(e)

__device__ float g_Q[B_*N_*C_];
__device__ float g_K[B_*N_*C_];
__device__ float g_V[B_*N_*C_];
__device__ float g_O[(long)B_*NW_*M_*C_];
__device__ float g_D[B_*NW_*M_];

__device__ __forceinline__ unsigned tf32u(float x) {
    unsigned u; asm("cvt.rna.tf32.f32 %0, %1;" : "=r"(u) : "f"(x)); return u;
}
__device__ __forceinline__ float ex2(float x) {
    float y; asm("ex2.approx.f32 %0, %1;" : "=f"(y) : "f"(x)); return y;
}
__device__ __forceinline__ void mma8(float d[4], const unsigned a[4], unsigned b0, unsigned b1) {
    asm volatile("mma.sync.aligned.m16n8k8.row.col.f32.tf32.tf32.f32 "
        "{%0,%1,%2,%3},{%4,%5,%6,%7},{%8,%9},{%0,%1,%2,%3};"
        : "+f"(d[0]), "+f"(d[1]), "+f"(d[2]), "+f"(d[3])
        : "r"(a[0]), "r"(a[1]), "r"(a[2]), "r"(a[3]), "r"(b0), "r"(b1));
}

// ================= Kernel 1: QKV projection, tf32, 512 thr, single wave =================
// grid 128 x 512 thr. Each CTA: 256 rows (2 iterations of 128). 16 warps:
// warp = (row-group 0..7) x (j-half 0..1); each warp: 16 rows x 12 n-tiles.
__global__ __launch_bounds__(512) void qkv_kernel(const float* __restrict__ x,
                                                  const float* __restrict__ Wq,
                                                  const float* __restrict__ Wk,
                                                  const float* __restrict__ Wv) {
    extern __shared__ unsigned smw[];   // Wt[192*WST]
    const int tid = threadIdx.x;
    const int wid = tid >> 5, lane = tid & 31;
    const int g = lane >> 2, t4 = lane & 3;
    const int rw = wid >> 1;            // row-group within 128-row block
    const int jh = (wid & 1) * 12;      // n-tile half: 0 or 12

    // stage W^T once: Wt[n][k] = W[k][n]
    const float* Wm[3] = {Wq, Wk, Wv};
    for (int idx = tid; idx < 192*64; idx += 512) {
        int k = idx / 192, nn = idx % 192;
        smw[nn*WST + k] = tf32u(Wm[nn >> 6][k*64 + (nn & 63)]);
    }
    __syncthreads();

    #pragma unroll
    for (int it = 0; it < 2; it++) {
        const long row0 = (long)blockIdx.x*256 + it*128 + 16*rw;
        const float* x0 = x + (row0 + g)*C_;
        const float* x1 = x0 + 8*C_;
        unsigned a[8][4];
        #pragma unroll
        for (int s = 0; s < 8; s++) {
            a[s][0] = tf32u(x0[8*s + t4]);
            a[s][1] = tf32u(x1[8*s + t4]);
            a[s][2] = tf32u(x0[8*s + t4 + 4]);
            a[s][3] = tf32u(x1[8*s + t4 + 4]);
        }

        float acc[12][4];
        #pragma unroll
        for (int j = 0; j < 12; j++)
            #pragma unroll
            for (int q = 0; q < 4; q++) acc[j][q] = 0.f;

        #pragma unroll
        for (int s = 0; s < 8; s++) {
            #pragma unroll
            for (int j = 0; j < 12; j++) {
                unsigned b0 = smw[(8*(jh + j) + g)*WST + 8*s + t4];
                unsigned b1 = smw[(8*(jh + j) + g)*WST + 8*s + t4 + 4];
                mma8(acc[j], a[s], b0, b1);
            }
        }

        const long r0 = row0 + g, r1 = r0 + 8;
        #pragma unroll
        for (int j = 0; j < 12; j++) {
            int jj = jh + j;
            int col = ((jj & 7) << 3) + 2*t4;
            float* dst = (jj < 8) ? g_Q : (jj < 16) ? g_K : g_V;
            float sc = (jj < 8) ? SCALE_LOG2 : 1.0f;
            *(float2*)&dst[r0*C_ + col] = make_float2(acc[j][0]*sc, acc[j][1]*sc);
            *(float2*)&dst[r1*C_ + col] = make_float2(acc[j][2]*sc, acc[j][3]*sc);
        }
    }
}

// ==== Kernel 2: tf32 flash attention — 128-key steps, two 64-key sub-passes ====
__global__ __launch_bounds__(256, 1) void attn_kernel() {
    extern __shared__ unsigned smu[];
    unsigned* Ks = smu;               // [128][KST]
    unsigned* Vs = smu + 128*KST;     // [128][VST]

    const int tid  = threadIdx.x;
    const int wid  = tid >> 5, lane = tid & 31;
    const int g    = lane >> 2, t4 = lane & 3;
    const int blk  = blockIdx.x;
    const int qb   = (NQB - 1) - blk / (B_*NW_);   // heaviest first (LPT)
    const int w    = blk % (B_*NW_);
    const int b    = w / NW_, wi = w % NW_;

    int base, r;
    if      (wi < 4) { base = wi*2048;     r = 1; }
    else if (wi < 6) { base = (wi-4)*4096; r = 2; }
    else             { base = 0;           r = 4; }

    const float* Qg = g_Q + ((long)b*N_ + base)*C_;
    const float* Kg = g_K + ((long)b*N_ + base)*C_;
    const float* Vg = g_V + ((long)b*N_ + base)*C_;
    const int rs = r * C_;

    const int row0 = qb*QB_ROWS + 32*wid;
    unsigned qa[2][8][4];
    #pragma unroll
    for (int mt = 0; mt < 2; mt++) {
        const float* q0 = Qg + (long)(row0 + 16*mt + g)*rs;
        const float* q1 = q0 + (long)8*rs;
        #pragma unroll
        for (int s = 0; s < 8; s++) {
            qa[mt][s][0] = tf32u(q0[8*s + t4]);
            qa[mt][s][1] = tf32u(q1[8*s + t4]);
            qa[mt][s][2] = tf32u(q0[8*s + t4 + 4]);
            qa[mt][s][3] = tf32u(q1[8*s + t4 + 4]);
        }
    }

    float oacc[2][8][4];
    float mrow[2][2], lrow[2][2];
    #pragma unroll
    for (int mt = 0; mt < 2; mt++) {
        mrow[mt][0] = mrow[mt][1] = -1e30f;
        lrow[mt][0] = lrow[mt][1] = 0.f;
        #pragma unroll
        for (int j = 0; j < 8; j++)
            #pragma unroll
            for (int q = 0; q < 4; q++) oacc[mt][j][q] = 0.f;
    }

    const int nks = 2*qb + 2;          // 128-key steps
    for (int ks = 0; ks < nks; ks++) {
        __syncthreads();
        #pragma unroll
        for (int i = 0; i < 8; i++) {
            int l = tid + i*256;
            int slot = l >> 4, cg = (l & 15) << 2;
            int srck = (slot & ~7) | ((slot & 1) << 2) | ((slot & 7) >> 1);
            float4 kv = *(const float4*)(Kg + (long)(ks*128 + srck)*rs + cg);
            uint4 ku; ku.x = tf32u(kv.x); ku.y = tf32u(kv.y); ku.z = tf32u(kv.z); ku.w = tf32u(kv.w);
            *(uint4*)&Ks[slot*KST + cg] = ku;
            float4 vv = *(const float4*)(Vg + (long)(ks*128 + slot)*rs + cg);
            uint4 vu; vu.x = tf32u(vv.x); vu.y = tf32u(vv.y); vu.z = tf32u(vv.z); vu.w = tf32u(vv.w);
            *(uint4*)&Vs[slot*VST + cg] = vu;
        }
        __syncthreads();

        #pragma unroll
        for (int half = 0; half < 2; half++) {
            const unsigned* Ksh = Ks + (half*64)*KST;
            const unsigned* Vsh = Vs + (half*64)*VST;
            const int kbase = ks*128 + half*64;

            float sacc[2][8][4];
            #pragma unroll
            for (int mt = 0; mt < 2; mt++)
                #pragma unroll
                for (int j = 0; j < 8; j++)
                    #pragma unroll
                    for (int q = 0; q < 4; q++) sacc[mt][j][q] = 0.f;

            #pragma unroll
            for (int s = 0; s < 8; s++) {
                #pragma unroll
                for (int j = 0; j < 8; j++) {
                    unsigned b0 = Ksh[(8*j + g)*KST + 8*s + t4];
                    unsigned b1 = Ksh[(8*j + g)*KST + 8*s + t4 + 4];
                    mma8(sacc[0][j], qa[0][s], b0, b1);
                    mma8(sacc[1][j], qa[1][s], b0, b1);
                }
            }

            if (ks >= 2*qb) {
                #pragma unroll
                for (int mt = 0; mt < 2; mt++) {
                    int r0_ = row0 + 16*mt + g, r1_ = r0_ + 8;
                    #pragma unroll
                    for (int j = 0; j < 8; j++) {
                        int k0 = kbase + 8*j + t4, k1 = k0 + 4;
                        if (k0 > r0_) sacc[mt][j][0] = -1e30f;
                        if (k1 > r0_) sacc[mt][j][1] = -1e30f;
                        if (k0 > r1_) sacc[mt][j][2] = -1e30f;
                        if (k1 > r1_) sacc[mt][j][3] = -1e30f;
                    }
                }
            }

            #pragma unroll
            for (int mt = 0; mt < 2; mt++) {
                float rm0 = -1e30f, rm1 = -1e30f;
                #pragma unroll
                for (int j = 0; j < 8; j++) {
                    rm0 = fmaxf(rm0, fmaxf(sacc[mt][j][0], sacc[mt][j][1]));
                    rm1 = fmaxf(rm1, fmaxf(sacc[mt][j][2], sacc[mt][j][3]));
                }
                rm0 = fmaxf(rm0, __shfl_xor_sync(0xffffffffu, rm0, 1));
                rm0 = fmaxf(rm0, __shfl_xor_sync(0xffffffffu, rm0, 2));
                rm1 = fmaxf(rm1, __shfl_xor_sync(0xffffffffu, rm1, 1));
                rm1 = fmaxf(rm1, __shfl_xor_sync(0xffffffffu, rm1, 2));
                float mn0 = fmaxf(mrow[mt][0], rm0), mn1 = fmaxf(mrow[mt][1], rm1);
                float c0 = ex2(mrow[mt][0] - mn0),   c1 = ex2(mrow[mt][1] - mn1);
                mrow[mt][0] = mn0; mrow[mt][1] = mn1;
                float rs0 = 0.f, rs1 = 0.f;
                #pragma unroll
                for (int j = 0; j < 8; j++) {
                    float p0 = ex2(sacc[mt][j][0] - mn0); rs0 += p0; sacc[mt][j][0] = p0;
                    float p1 = ex2(sacc[mt][j][1] - mn0); rs0 += p1; sacc[mt][j][1] = p1;
                    float p2 = ex2(sacc[mt][j][2] - mn1); rs1 += p2; sacc[mt][j][2] = p2;
                    float p3 = ex2(sacc[mt][j][3] - mn1); rs1 += p3; sacc[mt][j][3] = p3;
                }
                rs0 += __shfl_xor_sync(0xffffffffu, rs0, 1);
                rs0 += __shfl_xor_sync(0xffffffffu, rs0, 2);
                rs1 += __shfl_xor_sync(0xffffffffu, rs1, 1);
                rs1 += __shfl_xor_sync(0xffffffffu, rs1, 2);
                lrow[mt][0] = lrow[mt][0]*c0 + rs0;
                lrow[mt][1] = lrow[mt][1]*c1 + rs1;
                #pragma unroll
                for (int jv = 0; jv < 8; jv++) {
                    oacc[mt][jv][0] *= c0; oacc[mt][jv][1] *= c0;
                    oacc[mt][jv][2] *= c1; oacc[mt][jv][3] *= c1;
                }
            }

            #pragma unroll
            for (int s2 = 0; s2 < 8; s2++) {
                unsigned pa0[4] = { tf32u(sacc[0][s2][0]), tf32u(sacc[0][s2][2]),
                                    tf32u(sacc[0][s2][1]), tf32u(sacc[0][s2][3]) };
                unsigned pa1[4] = { tf32u(sacc[1][s2][0]), tf32u(sacc[1][s2][2]),
                                    tf32u(sacc[1][s2][1]), tf32u(sacc[1][s2][3]) };
                #pragma unroll
                for (int jv = 0; jv < 8; jv++) {
                    unsigned b0 = Vsh[(8*s2 + t4)*VST + 8*jv + g];
                    unsigned b1 = Vsh[(8*s2 + t4 + 4)*VST + 8*jv + g];
                    mma8(oacc[0][jv], pa0, b0, b1);
                    mma8(oacc[1][jv], pa1, b0, b1);
                }
            }
        }
    }

    float* Og = g_O + (long)(b*NW_ + wi)*M_*C_;
    float* Dg = g_D + (long)(b*NW_ + wi)*M_;
    #pragma unroll
    for (int mt = 0; mt < 2; mt++) {
        int r0_ = row0 + 16*mt + g, r1_ = r0_ + 8;
        float i0 = 1.0f / lrow[mt][0], i1 = 1.0f / lrow[mt][1];
        #pragma unroll
        for (int jv = 0; jv < 8; jv++) {
            *(float2*)&Og[(long)r0_*C_ + 8*jv + 2*t4] =
                make_float2(oacc[mt][jv][0]*i0, oacc[mt][jv][1]*i0);
            *(float2*)&Og[(long)r1_*C_ + 8*jv + 2*t4] =
                make_float2(oacc[mt][jv][2]*i1, oacc[mt][jv][3]*i1);
        }
        if (t4 == 0) {
            Dg[r0_] = lrow[mt][0] * ex2(mrow[mt][0]);
            Dg[r1_] = lrow[mt][1] * ex2(mrow[mt][1]);
        }
    }
}

// ============================ Kernel 3: mix ============================
__global__ __launch_bounds__(256) void mix_kernel(float* __restrict__ out) {
    const int tid = threadIdx.x;
    const int c = tid & 63;
    const int gp = blockIdx.x*4 + (tid >> 6);
    const int b = gp >> 13;
    const int p = gp & (N_-1);

    int w0 = p >> 11, r0 = p & 2047;
    long i0 = (long)(b*NW_ + w0)*M_ + r0;
    float d0 = g_D[i0];
    float dsum = d0;
    float num  = d0 * g_O[i0*C_ + c];

    if ((p & 1) == 0) {
        int w1 = 4 + (p >> 12), r1 = (p & 4095) >> 1;
        long i1 = (long)(b*NW_ + w1)*M_ + r1;
        float d1 = g_D[i1];
        dsum += d1;
        num  += d1 * g_O[i1*C_ + c];
    }
    if ((p & 3) == 0) {
        long i2 = (long)(b*NW_ + 6)*M_ + (p >> 2);
        float d2 = g_D[i2];
        dsum += d2;
        num  += d2 * g_O[i2*C_ + c];
    }
    out[((long)b*N_ + p)*C_ + c] = num / dsum;
}

// =======================================================================
extern "C" void kernel_launch(void* const* d_in, const int* in_sizes, int n_in,
                              void* d_out, int out_size) {
    (void)in_sizes; (void)n_in; (void)out_size;
    const float* x  = (const float*)d_in[0];
    const float* Wq = (const float*)d_in[1];
    const float* Wk = (const float*)d_in[2];
    const float* Wv = (const float*)d_in[3];
    float* out = (float*)d_out;

    const int smem1 = 192*WST*4;                    // 52224 B
    const int smem2 = (128*KST + 128*VST) * 4;      // 71680 B
    cudaFuncSetAttribute(qkv_kernel,  cudaFuncAttributeMaxDynamicSharedMemorySize, smem1);
    cudaFuncSetAttribute(attn_kernel, cudaFuncAttributeMaxDynamicSharedMemorySize, smem2);

    qkv_kernel<<<(B_*N_)/256, 512, smem1>>>(x, Wq, Wk, Wv);
    attn_kernel<<<NQB * B_ * NW_, 256, smem2>>>();
    mix_kernel<<<(B_*N_)/4, 256>>>(out);
}

// round 10
// speedup vs baseline: 1.2280x; 1.0133x over previous
#include <cuda_runtime.h>

#define B_  4
#define N_  8192
#define C_  64
#define M_  2048
#define NW_ 7
#define QB_ROWS 256
#define NQB 8
#define KST 68
#define VSTW 68          // Vt row stride in 32-bit words (fp16 pairs)
#define SCALE_LOG2 0.18033688011112042f  // (1/8) * log2(e)

__device__ float g_Q[B_*N_*C_];
__device__ float g_K[B_*N_*C_];
__device__ float g_V[B_*N_*C_];
__device__ float g_O[(long)B_*NW_*M_*C_];
__device__ float g_D[B_*NW_*M_];

__device__ __forceinline__ unsigned tf32u(float x) {
    unsigned u; asm("cvt.rna.tf32.f32 %0, %1;" : "=r"(u) : "f"(x)); return u;
}
__device__ __forceinline__ float ex2(float x) {
    float y; asm("ex2.approx.f32 %0, %1;" : "=f"(y) : "f"(x)); return y;
}
__device__ __forceinline__ void mma8(float d[4], const unsigned a[4], unsigned b0, unsigned b1) {
    asm volatile("mma.sync.aligned.m16n8k8.row.col.f32.tf32.tf32.f32 "
        "{%0,%1,%2,%3},{%4,%5,%6,%7},{%8,%9},{%0,%1,%2,%3};"
        : "+f"(d[0]), "+f"(d[1]), "+f"(d[2]), "+f"(d[3])
        : "r"(a[0]), "r"(a[1]), "r"(a[2]), "r"(a[3]), "r"(b0), "r"(b1));
}
__device__ __forceinline__ void mma16(float d[4], unsigned a0, unsigned a1, unsigned a2,
                                      unsigned a3, unsigned b0, unsigned b1) {
    asm volatile("mma.sync.aligned.m16n8k16.row.col.f32.f16.f16.f32 "
        "{%0,%1,%2,%3},{%4,%5,%6,%7},{%8,%9},{%0,%1,%2,%3};"
        : "+f"(d[0]), "+f"(d[1]), "+f"(d[2]), "+f"(d[3])
        : "r"(a0), "r"(a1), "r"(a2), "r"(a3), "r"(b0), "r"(b1));
}
// pack two f32 -> f16x2: lo half = LO (even k), hi half = HI (odd k)
#define PACK2(D, HI, LO) asm("cvt.rn.f16x2.f32 %0, %1, %2;" : "=r"(D) : "f"(HI), "f"(LO))

// ============================ Kernel 1: QKV (scalar fp32, proven 26.6us) ============================
__global__ __launch_bounds__(256) void qkv_kernel(const float* __restrict__ x,
                                                  const float* __restrict__ Wq,
                                                  const float* __restrict__ Wk,
                                                  const float* __restrict__ Wv) {
    extern __shared__ float sm1[];
    float* xT = sm1;
    float* Ws = sm1 + 4096;
    const int tid = threadIdx.x;
    const long rowbase = (long)blockIdx.x * 64;

    #pragma unroll
    for (int k = 0; k < 4; k++) {
        int l = tid + k*256;
        int row = l & 63, cg = l >> 6;
        float4 v = *(const float4*)(x + (rowbase + row)*C_ + cg*4);
        xT[(cg*4+0)*64 + row] = v.x;
        xT[(cg*4+1)*64 + row] = v.y;
        xT[(cg*4+2)*64 + row] = v.z;
        xT[(cg*4+3)*64 + row] = v.w;
    }
    {
        const float* Wm[3] = {Wq, Wk, Wv};
        #pragma unroll
        for (int m = 0; m < 3; m++)
            #pragma unroll
            for (int k = 0; k < 4; k++) {
                int l = tid + k*256;
                int cc = l >> 4, jg = l & 15;
                *(float4*)&Ws[cc*192 + m*64 + jg*4] = *(const float4*)(Wm[m] + cc*64 + jg*4);
            }
    }
    __syncthreads();

    const int ty = tid >> 4, tx = tid & 15;
    float acc[3][4][4];
    #pragma unroll
    for (int m = 0; m < 3; m++)
        #pragma unroll
        for (int i = 0; i < 4; i++)
            #pragma unroll
            for (int j = 0; j < 4; j++) acc[m][i][j] = 0.f;

    const float* xp = xT + ty*4;
    #pragma unroll 4
    for (int cc = 0; cc < 64; cc++) {
        float4 xv = *(const float4*)(xp + cc*64);
        float4 w0 = *(const float4*)(Ws + cc*192 +   0 + tx*4);
        float4 w1 = *(const float4*)(Ws + cc*192 +  64 + tx*4);
        float4 w2 = *(const float4*)(Ws + cc*192 + 128 + tx*4);
        float xs[4] = {xv.x, xv.y, xv.z, xv.w};
        float wq[4] = {w0.x, w0.y, w0.z, w0.w};
        float wk[4] = {w1.x, w1.y, w1.z, w1.w};
        float wv[4] = {w2.x, w2.y, w2.z, w2.w};
        #pragma unroll
        for (int i = 0; i < 4; i++)
            #pragma unroll
            for (int j = 0; j < 4; j++) {
                acc[0][i][j] += xs[i]*wq[j];
                acc[1][i][j] += xs[i]*wk[j];
                acc[2][i][j] += xs[i]*wv[j];
            }
    }
    #pragma unroll
    for (int i = 0; i < 4; i++) {
        long rr = (rowbase + ty*4 + i)*C_ + tx*4;
        *(float4*)&g_Q[rr] = make_float4(acc[0][i][0]*SCALE_LOG2, acc[0][i][1]*SCALE_LOG2,
                                         acc[0][i][2]*SCALE_LOG2, acc[0][i][3]*SCALE_LOG2);
        *(float4*)&g_K[rr] = make_float4(acc[1][i][0], acc[1][i][1], acc[1][i][2], acc[1][i][3]);
        *(float4*)&g_V[rr] = make_float4(acc[2][i][0], acc[2][i][1], acc[2][i][2], acc[2][i][3]);
    }
}

// ==== Kernel 2: flash attention — tf32 S, fp16 PV, 128-key steps ====
__global__ __launch_bounds__(256, 1) void attn_kernel() {
    extern __shared__ unsigned smu[];
    unsigned* Ks   = smu;                 // [128][KST] tf32 bits
    unsigned* Vt32 = smu + 128*KST;       // [64 c][VSTW] fp16x2 (keys pair-packed)

    const int tid  = threadIdx.x;
    const int wid  = tid >> 5, lane = tid & 31;
    const int g    = lane >> 2, t4 = lane & 3;
    const int blk  = blockIdx.x;
    const int qb   = (NQB - 1) - blk / (B_*NW_);   // heaviest first (LPT)
    const int w    = blk % (B_*NW_);
    const int b    = w / NW_, wi = w % NW_;

    int base, r;
    if      (wi < 4) { base = wi*2048;     r = 1; }
    else if (wi < 6) { base = (wi-4)*4096; r = 2; }
    else             { base = 0;           r = 4; }

    const float* Qg = g_Q + ((long)b*N_ + base)*C_;
    const float* Kg = g_K + ((long)b*N_ + base)*C_;
    const float* Vg = g_V + ((long)b*N_ + base)*C_;
    const int rs = r * C_;

    const int row0 = qb*QB_ROWS + 32*wid;
    unsigned qa[2][8][4];
    #pragma unroll
    for (int mt = 0; mt < 2; mt++) {
        const float* q0 = Qg + (long)(row0 + 16*mt + g)*rs;
        const float* q1 = q0 + (long)8*rs;
        #pragma unroll
        for (int s = 0; s < 8; s++) {
            qa[mt][s][0] = tf32u(q0[8*s + t4]);
            qa[mt][s][1] = tf32u(q1[8*s + t4]);
            qa[mt][s][2] = tf32u(q0[8*s + t4 + 4]);
            qa[mt][s][3] = tf32u(q1[8*s + t4 + 4]);
        }
    }

    float oacc[2][8][4];
    float mrow[2][2], lrow[2][2];
    #pragma unroll
    for (int mt = 0; mt < 2; mt++) {
        mrow[mt][0] = mrow[mt][1] = -1e30f;
        lrow[mt][0] = lrow[mt][1] = 0.f;
        #pragma unroll
        for (int j = 0; j < 8; j++)
            #pragma unroll
            for (int q = 0; q < 4; q++) oacc[mt][j][q] = 0.f;
    }

    const int nks = 2*qb + 2;          // 128-key steps
    for (int ks = 0; ks < nks; ks++) {
        __syncthreads();
        // ---- fill K (natural row order, tf32) ----
        #pragma unroll
        for (int i = 0; i < 8; i++) {
            int l = tid + i*256;
            int slot = l >> 4, cg = (l & 15) << 2;
            float4 kv = *(const float4*)(Kg + (long)(ks*128 + slot)*rs + cg);
            uint4 ku; ku.x = tf32u(kv.x); ku.y = tf32u(kv.y); ku.z = tf32u(kv.z); ku.w = tf32u(kv.w);
            *(uint4*)&Ks[slot*KST + cg] = ku;
        }
        // ---- fill V transposed fp16: Vt[c][keypair] ----
        #pragma unroll
        for (int i = 0; i < 4; i++) {
            int l = tid + i*256;
            int kp = ((l >> 7) << 3) | (l & 7);    // keypair 0..63
            int c0 = ((l >> 3) & 15) << 2;
            const float* va = Vg + (long)(ks*128 + 2*kp)*rs + c0;
            float4 a4 = *(const float4*)va;
            float4 b4 = *(const float4*)(va + rs);
            unsigned p0, p1, p2, p3;
            PACK2(p0, b4.x, a4.x);
            PACK2(p1, b4.y, a4.y);
            PACK2(p2, b4.z, a4.z);
            PACK2(p3, b4.w, a4.w);
            Vt32[(c0+0)*VSTW + kp] = p0;
            Vt32[(c0+1)*VSTW + kp] = p1;
            Vt32[(c0+2)*VSTW + kp] = p2;
            Vt32[(c0+3)*VSTW + kp] = p3;
        }
        __syncthreads();

        #pragma unroll
        for (int half = 0; half < 2; half++) {
            const unsigned* Ksh = Ks + (half*64)*KST;
            const int kbase = ks*128 + half*64;

            // ---- S = Q K^T (tf32) ----
            float sacc[2][8][4];
            #pragma unroll
            for (int mt = 0; mt < 2; mt++)
                #pragma unroll
                for (int j = 0; j < 8; j++)
                    #pragma unroll
                    for (int q = 0; q < 4; q++) sacc[mt][j][q] = 0.f;

            #pragma unroll
            for (int s = 0; s < 8; s++) {
                #pragma unroll
                for (int j = 0; j < 8; j++) {
                    unsigned b0 = Ksh[(8*j + g)*KST + 8*s + t4];
                    unsigned b1 = Ksh[(8*j + g)*KST + 8*s + t4 + 4];
                    mma8(sacc[0][j], qa[0][s], b0, b1);
                    mma8(sacc[1][j], qa[1][s], b0, b1);
                }
            }

            // ---- causal mask (C cols: 8j+2t4, 8j+2t4+1) ----
            if (ks >= 2*qb) {
                #pragma unroll
                for (int mt = 0; mt < 2; mt++) {
                    int r0_ = row0 + 16*mt + g, r1_ = r0_ + 8;
                    #pragma unroll
                    for (int j = 0; j < 8; j++) {
                        int k0 = kbase + 8*j + 2*t4, k1 = k0 + 1;
                        if (k0 > r0_) sacc[mt][j][0] = -1e30f;
                        if (k1 > r0_) sacc[mt][j][1] = -1e30f;
                        if (k0 > r1_) sacc[mt][j][2] = -1e30f;
                        if (k1 > r1_) sacc[mt][j][3] = -1e30f;
                    }
                }
            }

            // ---- online softmax (log2 domain) ----
            #pragma unroll
            for (int mt = 0; mt < 2; mt++) {
                float rm0 = -1e30f, rm1 = -1e30f;
                #pragma unroll
                for (int j = 0; j < 8; j++) {
                    rm0 = fmaxf(rm0, fmaxf(sacc[mt][j][0], sacc[mt][j][1]));
                    rm1 = fmaxf(rm1, fmaxf(sacc[mt][j][2], sacc[mt][j][3]));
                }
                rm0 = fmaxf(rm0, __shfl_xor_sync(0xffffffffu, rm0, 1));
                rm0 = fmaxf(rm0, __shfl_xor_sync(0xffffffffu, rm0, 2));
                rm1 = fmaxf(rm1, __shfl_xor_sync(0xffffffffu, rm1, 1));
                rm1 = fmaxf(rm1, __shfl_xor_sync(0xffffffffu, rm1, 2));
                float mn0 = fmaxf(mrow[mt][0], rm0), mn1 = fmaxf(mrow[mt][1], rm1);
                float c0 = ex2(mrow[mt][0] - mn0),   c1 = ex2(mrow[mt][1] - mn1);
                mrow[mt][0] = mn0; mrow[mt][1] = mn1;
                float rs0 = 0.f, rs1 = 0.f;
                #pragma unroll
                for (int j = 0; j < 8; j++) {
                    float p0 = ex2(sacc[mt][j][0] - mn0); rs0 += p0; sacc[mt][j][0] = p0;
                    float p1 = ex2(sacc[mt][j][1] - mn0); rs0 += p1; sacc[mt][j][1] = p1;
                    float p2 = ex2(sacc[mt][j][2] - mn1); rs1 += p2; sacc[mt][j][2] = p2;
                    float p3 = ex2(sacc[mt][j][3] - mn1); rs1 += p3; sacc[mt][j][3] = p3;
                }
                rs0 += __shfl_xor_sync(0xffffffffu, rs0, 1);
                rs0 += __shfl_xor_sync(0xffffffffu, rs0, 2);
                rs1 += __shfl_xor_sync(0xffffffffu, rs1, 1);
                rs1 += __shfl_xor_sync(0xffffffffu, rs1, 2);
                lrow[mt][0] = lrow[mt][0]*c0 + rs0;
                lrow[mt][1] = lrow[mt][1]*c1 + rs1;
                #pragma unroll
                for (int jv = 0; jv < 8; jv++) {
                    oacc[mt][jv][0] *= c0; oacc[mt][jv][1] *= c0;
                    oacc[mt][jv][2] *= c1; oacc[mt][jv][3] *= c1;
                }
            }

            // ---- O += P V  (fp16 m16n8k16; P packed from S C-frags) ----
            #pragma unroll
            for (int u = 0; u < 4; u++) {
                unsigned a00, a01, a02, a03, a10, a11, a12, a13;
                PACK2(a00, sacc[0][2*u  ][1], sacc[0][2*u  ][0]);
                PACK2(a01, sacc[0][2*u  ][3], sacc[0][2*u  ][2]);
                PACK2(a02, sacc[0][2*u+1][1], sacc[0][2*u+1][0]);
                PACK2(a03, sacc[0][2*u+1][3], sacc[0][2*u+1][2]);
                PACK2(a10, sacc[1][2*u  ][1], sacc[1][2*u  ][0]);
                PACK2(a11, sacc[1][2*u  ][3], sacc[1][2*u  ][2]);
                PACK2(a12, sacc[1][2*u+1][1], sacc[1][2*u+1][0]);
                PACK2(a13, sacc[1][2*u+1][3], sacc[1][2*u+1][2]);
                const int kpb = half*32 + 8*u;
                #pragma unroll
                for (int jv = 0; jv < 8; jv++) {
                    unsigned b0 = Vt32[(8*jv + g)*VSTW + kpb + t4];
                    unsigned b1 = Vt32[(8*jv + g)*VSTW + kpb + t4 + 4];
                    mma16(oacc[0][jv], a00, a01, a02, a03, b0, b1);
                    mma16(oacc[1][jv], a10, a11, a12, a13, b0, b1);
                }
            }
        }
    }

    // ---- epilogue: normalized O + denominator d = l * 2^m ----
    float* Og = g_O + (long)(b*NW_ + wi)*M_*C_;
    float* Dg = g_D + (long)(b*NW_ + wi)*M_;
    #pragma unroll
    for (int mt = 0; mt < 2; mt++) {
        int r0_ = row0 + 16*mt + g, r1_ = r0_ + 8;
        float i0 = 1.0f / lrow[mt][0], i1 = 1.0f / lrow[mt][1];
        #pragma unroll
        for (int jv = 0; jv < 8; jv++) {
            *(float2*)&Og[(long)r0_*C_ + 8*jv + 2*t4] =
                make_float2(oacc[mt][jv][0]*i0, oacc[mt][jv][1]*i0);
            *(float2*)&Og[(long)r1_*C_ + 8*jv + 2*t4] =
                make_float2(oacc[mt][jv][2]*i1, oacc[mt][jv][3]*i1);
        }
        if (t4 == 0) {
            Dg[r0_] = lrow[mt][0] * ex2(mrow[mt][0]);
            Dg[r1_] = lrow[mt][1] * ex2(mrow[mt][1]);
        }
    }
}

// ============================ Kernel 3: mix ============================
__global__ __launch_bounds__(256) void mix_kernel(float* __restrict__ out) {
    const int tid = threadIdx.x;
    const int c = tid & 63;
    const int gp = blockIdx.x*4 + (tid >> 6);
    const int b = gp >> 13;
    const int p = gp & (N_-1);

    int w0 = p >> 11, r0 = p & 2047;
    long i0 = (long)(b*NW_ + w0)*M_ + r0;
    float d0 = g_D[i0];
    float dsum = d0;
    float num  = d0 * g_O[i0*C_ + c];

    if ((p & 1) == 0) {
        int w1 = 4 + (p >> 12), r1 = (p & 4095) >> 1;
        long i1 = (long)(b*NW_ + w1)*M_ + r1;
        float d1 = g_D[i1];
        dsum += d1;
        num  += d1 * g_O[i1*C_ + c];
    }
    if ((p & 3) == 0) {
        long i2 = (long)(b*NW_ + 6)*M_ + (p >> 2);
        float d2 = g_D[i2];
        dsum += d2;
        num  += d2 * g_O[i2*C_ + c];
    }
    out[((long)b*N_ + p)*C_ + c] = num / dsum;
}

// =======================================================================
extern "C" void kernel_launch(void* const* d_in, const int* in_sizes, int n_in,
                              void* d_out, int out_size) {
    (void)in_sizes; (void)n_in; (void)out_size;
    const float* x  = (const float*)d_in[0];
    const float* Wq = (const float*)d_in[1];
    const float* Wk = (const float*)d_in[2];
    const float* Wv = (const float*)d_in[3];
    float* out = (float*)d_out;

    const int smem1 = (64*64 + 64*192) * 4;            // 64 KB
    const int smem2 = (128*KST + 64*VSTW) * 4;         // 52224 B
    cudaFuncSetAttribute(qkv_kernel,  cudaFuncAttributeMaxDynamicSharedMemorySize, smem1);
    cudaFuncSetAttribute(attn_kernel, cudaFuncAttributeMaxDynamicSharedMemorySize, smem2);

    qkv_kernel<<<(B_*N_)/64, 256, smem1>>>(x, Wq, Wk, Wv);
    attn_kernel<<<NQB * B_ * NW_, 256, smem2>>>();
    mix_kernel<<<(B_*N_)/4, 256>>>(out);
}

// round 11
// speedup vs baseline: 1.4064x; 1.1453x over previous
#include <cuda_runtime.h>

#define B_  4
#define N_  8192
#define C_  64
#define M_  2048
#define NW_ 7
#define QB_ROWS 256
#define NQB 8
#define KST2 36          // K smem row stride in 32-bit words (fp16 c-pairs)
#define VSTW 68          // Vt row stride in 32-bit words (fp16 key-pairs)
#define SCALE_LOG2 0.18033688011112042f  // (1/8) * log2(e)

__device__ float g_Q[B_*N_*C_];
__device__ float g_K[B_*N_*C_];
__device__ float g_V[B_*N_*C_];
__device__ float g_O[(long)B_*NW_*M_*C_];
__device__ float g_D[B_*NW_*M_];

__device__ __forceinline__ float ex2(float x) {
    float y; asm("ex2.approx.f32 %0, %1;" : "=f"(y) : "f"(x)); return y;
}
__device__ __forceinline__ void mma16(float d[4], unsigned a0, unsigned a1, unsigned a2,
                                      unsigned a3, unsigned b0, unsigned b1) {
    asm volatile("mma.sync.aligned.m16n8k16.row.col.f32.f16.f16.f32 "
        "{%0,%1,%2,%3},{%4,%5,%6,%7},{%8,%9},{%0,%1,%2,%3};"
        : "+f"(d[0]), "+f"(d[1]), "+f"(d[2]), "+f"(d[3])
        : "r"(a0), "r"(a1), "r"(a2), "r"(a3), "r"(b0), "r"(b1));
}
// pack two f32 -> f16x2: lo half = LO (even k), hi half = HI (odd k)
#define PACK2(D, HI, LO) asm("cvt.rn.f16x2.f32 %0, %1, %2;" : "=r"(D) : "f"(HI), "f"(LO))

// ============================ Kernel 1: QKV (scalar fp32, proven 26.4us) ============================
__global__ __launch_bounds__(256) void qkv_kernel(const float* __restrict__ x,
                                                  const float* __restrict__ Wq,
                                                  const float* __restrict__ Wk,
                                                  const float* __restrict__ Wv) {
    extern __shared__ float sm1[];
    float* xT = sm1;
    float* Ws = sm1 + 4096;
    const int tid = threadIdx.x;
    const long rowbase = (long)blockIdx.x * 64;

    #pragma unroll
    for (int k = 0; k < 4; k++) {
        int l = tid + k*256;
        int row = l & 63, cg = l >> 6;
        float4 v = *(const float4*)(x + (rowbase + row)*C_ + cg*4);
        xT[(cg*4+0)*64 + row] = v.x;
        xT[(cg*4+1)*64 + row] = v.y;
        xT[(cg*4+2)*64 + row] = v.z;
        xT[(cg*4+3)*64 + row] = v.w;
    }
    {
        const float* Wm[3] = {Wq, Wk, Wv};
        #pragma unroll
        for (int m = 0; m < 3; m++)
            #pragma unroll
            for (int k = 0; k < 4; k++) {
                int l = tid + k*256;
                int cc = l >> 4, jg = l & 15;
                *(float4*)&Ws[cc*192 + m*64 + jg*4] = *(const float4*)(Wm[m] + cc*64 + jg*4);
            }
    }
    __syncthreads();

    const int ty = tid >> 4, tx = tid & 15;
    float acc[3][4][4];
    #pragma unroll
    for (int m = 0; m < 3; m++)
        #pragma unroll
        for (int i = 0; i < 4; i++)
            #pragma unroll
            for (int j = 0; j < 4; j++) acc[m][i][j] = 0.f;

    const float* xp = xT + ty*4;
    #pragma unroll 4
    for (int cc = 0; cc < 64; cc++) {
        float4 xv = *(const float4*)(xp + cc*64);
        float4 w0 = *(const float4*)(Ws + cc*192 +   0 + tx*4);
        float4 w1 = *(const float4*)(Ws + cc*192 +  64 + tx*4);
        float4 w2 = *(const float4*)(Ws + cc*192 + 128 + tx*4);
        float xs[4] = {xv.x, xv.y, xv.z, xv.w};
        float wq[4] = {w0.x, w0.y, w0.z, w0.w};
        float wk[4] = {w1.x, w1.y, w1.z, w1.w};
        float wv[4] = {w2.x, w2.y, w2.z, w2.w};
        #pragma unroll
        for (int i = 0; i < 4; i++)
            #pragma unroll
            for (int j = 0; j < 4; j++) {
                acc[0][i][j] += xs[i]*wq[j];
                acc[1][i][j] += xs[i]*wk[j];
                acc[2][i][j] += xs[i]*wv[j];
            }
    }
    #pragma unroll
    for (int i = 0; i < 4; i++) {
        long rr = (rowbase + ty*4 + i)*C_ + tx*4;
        *(float4*)&g_Q[rr] = make_float4(acc[0][i][0]*SCALE_LOG2, acc[0][i][1]*SCALE_LOG2,
                                         acc[0][i][2]*SCALE_LOG2, acc[0][i][3]*SCALE_LOG2);
        *(float4*)&g_K[rr] = make_float4(acc[1][i][0], acc[1][i][1], acc[1][i][2], acc[1][i][3]);
        *(float4*)&g_V[rr] = make_float4(acc[2][i][0], acc[2][i][1], acc[2][i][2], acc[2][i][3]);
    }
}

// ==== Kernel 2: flash attention — full fp16 operands (fp32 accum), 128-key steps ====
__global__ __launch_bounds__(256, 1) void attn_kernel() {
    extern __shared__ unsigned smu[];
    unsigned* Ks16 = smu;                 // [128 key][KST2] fp16x2, c pair-packed
    unsigned* Vt32 = smu + 128*KST2;      // [64 c][VSTW]   fp16x2, key pair-packed

    const int tid  = threadIdx.x;
    const int wid  = tid >> 5, lane = tid & 31;
    const int g    = lane >> 2, t4 = lane & 3;
    const int blk  = blockIdx.x;
    const int qb   = (NQB - 1) - blk / (B_*NW_);   // heaviest first (LPT)
    const int w    = blk % (B_*NW_);
    const int b    = w / NW_, wi = w % NW_;

    int base, r;
    if      (wi < 4) { base = wi*2048;     r = 1; }
    else if (wi < 6) { base = (wi-4)*4096; r = 2; }
    else             { base = 0;           r = 4; }

    const float* Qg = g_Q + ((long)b*N_ + base)*C_;
    const float* Kg = g_K + ((long)b*N_ + base)*C_;
    const float* Vg = g_V + ((long)b*N_ + base)*C_;
    const int rs = r * C_;

    // ---- Q fragments, fp16-packed (32 regs total) ----
    const int row0 = qb*QB_ROWS + 32*wid;
    unsigned qa[2][4][4];
    #pragma unroll
    for (int mt = 0; mt < 2; mt++) {
        const float* q0 = Qg + (long)(row0 + 16*mt + g)*rs;
        const float* q1 = q0 + (long)8*rs;
        #pragma unroll
        for (int kc = 0; kc < 4; kc++) {
            int k0 = 16*kc + 2*t4;
            PACK2(qa[mt][kc][0], q0[k0+1], q0[k0]);
            PACK2(qa[mt][kc][1], q1[k0+1], q1[k0]);
            PACK2(qa[mt][kc][2], q0[k0+9], q0[k0+8]);
            PACK2(qa[mt][kc][3], q1[k0+9], q1[k0+8]);
        }
    }

    float oacc[2][8][4];
    float mrow[2][2], lrow[2][2];
    #pragma unroll
    for (int mt = 0; mt < 2; mt++) {
        mrow[mt][0] = mrow[mt][1] = -1e30f;
        lrow[mt][0] = lrow[mt][1] = 0.f;
        #pragma unroll
        for (int j = 0; j < 8; j++)
            #pragma unroll
            for (int q = 0; q < 4; q++) oacc[mt][j][q] = 0.f;
    }

    const int nks = 2*qb + 2;          // 128-key steps
    for (int ks = 0; ks < nks; ks++) {
        __syncthreads();
        // ---- fill K rows fp16 (c pair-packed): 128 keys x 32 words ----
        #pragma unroll
        for (int i = 0; i < 8; i++) {
            int l = tid + i*256;
            int slot = l >> 4, cg = (l & 15) << 2;
            float4 kv = *(const float4*)(Kg + (long)(ks*128 + slot)*rs + cg);
            unsigned w0, w1;
            PACK2(w0, kv.y, kv.x);
            PACK2(w1, kv.w, kv.z);
            Ks16[slot*KST2 + (cg >> 1)    ] = w0;
            Ks16[slot*KST2 + (cg >> 1) + 1] = w1;
        }
        // ---- fill V transposed fp16: Vt[c][keypair] ----
        #pragma unroll
        for (int i = 0; i < 4; i++) {
            int l = tid + i*256;
            int kp = ((l >> 7) << 3) | (l & 7);    // keypair 0..63
            int c0 = ((l >> 3) & 15) << 2;
            const float* va = Vg + (long)(ks*128 + 2*kp)*rs + c0;
            float4 a4 = *(const float4*)va;
            float4 b4 = *(const float4*)(va + rs);
            unsigned p0, p1, p2, p3;
            PACK2(p0, b4.x, a4.x);
            PACK2(p1, b4.y, a4.y);
            PACK2(p2, b4.z, a4.z);
            PACK2(p3, b4.w, a4.w);
            Vt32[(c0+0)*VSTW + kp] = p0;
            Vt32[(c0+1)*VSTW + kp] = p1;
            Vt32[(c0+2)*VSTW + kp] = p2;
            Vt32[(c0+3)*VSTW + kp] = p3;
        }
        __syncthreads();

        #pragma unroll
        for (int half = 0; half < 2; half++) {
            const int kbase = ks*128 + half*64;

            // ---- S = Q K^T (fp16 k16: 4 k-chunks) ----
            float sacc[2][8][4];
            #pragma unroll
            for (int mt = 0; mt < 2; mt++)
                #pragma unroll
                for (int j = 0; j < 8; j++)
                    #pragma unroll
                    for (int q = 0; q < 4; q++) sacc[mt][j][q] = 0.f;

            #pragma unroll
            for (int kc = 0; kc < 4; kc++) {
                #pragma unroll
                for (int j = 0; j < 8; j++) {
                    const unsigned* kr = Ks16 + (half*64 + 8*j + g)*KST2 + 8*kc + t4;
                    unsigned b0 = kr[0];
                    unsigned b1 = kr[4];
                    mma16(sacc[0][j], qa[0][kc][0], qa[0][kc][1], qa[0][kc][2], qa[0][kc][3], b0, b1);
                    mma16(sacc[1][j], qa[1][kc][0], qa[1][kc][1], qa[1][kc][2], qa[1][kc][3], b0, b1);
                }
            }

            // ---- causal mask (C cols: 8j+2t4, 8j+2t4+1) ----
            if (ks >= 2*qb) {
                #pragma unroll
                for (int mt = 0; mt < 2; mt++) {
                    int r0_ = row0 + 16*mt + g, r1_ = r0_ + 8;
                    #pragma unroll
                    for (int j = 0; j < 8; j++) {
                        int k0 = kbase + 8*j + 2*t4, k1 = k0 + 1;
                        if (k0 > r0_) sacc[mt][j][0] = -1e30f;
                        if (k1 > r0_) sacc[mt][j][1] = -1e30f;
                        if (k0 > r1_) sacc[mt][j][2] = -1e30f;
                        if (k1 > r1_) sacc[mt][j][3] = -1e30f;
                    }
                }
            }

            // ---- online softmax (log2 domain) ----
            #pragma unroll
            for (int mt = 0; mt < 2; mt++) {
                float rm0 = -1e30f, rm1 = -1e30f;
                #pragma unroll
                for (int j = 0; j < 8; j++) {
                    rm0 = fmaxf(rm0, fmaxf(sacc[mt][j][0], sacc[mt][j][1]));
                    rm1 = fmaxf(rm1, fmaxf(sacc[mt][j][2], sacc[mt][j][3]));
                }
                rm0 = fmaxf(rm0, __shfl_xor_sync(0xffffffffu, rm0, 1));
                rm0 = fmaxf(rm0, __shfl_xor_sync(0xffffffffu, rm0, 2));
                rm1 = fmaxf(rm1, __shfl_xor_sync(0xffffffffu, rm1, 1));
                rm1 = fmaxf(rm1, __shfl_xor_sync(0xffffffffu, rm1, 2));
                float mn0 = fmaxf(mrow[mt][0], rm0), mn1 = fmaxf(mrow[mt][1], rm1);
                float c0 = ex2(mrow[mt][0] - mn0),   c1 = ex2(mrow[mt][1] - mn1);
                mrow[mt][0] = mn0; mrow[mt][1] = mn1;
                float rs0 = 0.f, rs1 = 0.f;
                #pragma unroll
                for (int j = 0; j < 8; j++) {
                    float p0 = ex2(sacc[mt][j][0] - mn0); rs0 += p0; sacc[mt][j][0] = p0;
                    float p1 = ex2(sacc[mt][j][1] - mn0); rs0 += p1; sacc[mt][j][1] = p1;
                    float p2 = ex2(sacc[mt][j][2] - mn1); rs1 += p2; sacc[mt][j][2] = p2;
                    float p3 = ex2(sacc[mt][j][3] - mn1); rs1 += p3; sacc[mt][j][3] = p3;
                }
                rs0 += __shfl_xor_sync(0xffffffffu, rs0, 1);
                rs0 += __shfl_xor_sync(0xffffffffu, rs0, 2);
                rs1 += __shfl_xor_sync(0xffffffffu, rs1, 1);
                rs1 += __shfl_xor_sync(0xffffffffu, rs1, 2);
                lrow[mt][0] = lrow[mt][0]*c0 + rs0;
                lrow[mt][1] = lrow[mt][1]*c1 + rs1;
                #pragma unroll
                for (int jv = 0; jv < 8; jv++) {
                    oacc[mt][jv][0] *= c0; oacc[mt][jv][1] *= c0;
                    oacc[mt][jv][2] *= c1; oacc[mt][jv][3] *= c1;
                }
            }

            // ---- O += P V  (fp16 m16n8k16; P packed from S C-frags) ----
            #pragma unroll
            for (int u = 0; u < 4; u++) {
                unsigned a00, a01, a02, a03, a10, a11, a12, a13;
                PACK2(a00, sacc[0][2*u  ][1], sacc[0][2*u  ][0]);
                PACK2(a01, sacc[0][2*u  ][3], sacc[0][2*u  ][2]);
                PACK2(a02, sacc[0][2*u+1][1], sacc[0][2*u+1][0]);
                PACK2(a03, sacc[0][2*u+1][3], sacc[0][2*u+1][2]);
                PACK2(a10, sacc[1][2*u  ][1], sacc[1][2*u  ][0]);
                PACK2(a11, sacc[1][2*u  ][3], sacc[1][2*u  ][2]);
                PACK2(a12, sacc[1][2*u+1][1], sacc[1][2*u+1][0]);
                PACK2(a13, sacc[1][2*u+1][3], sacc[1][2*u+1][2]);
                const int kpb = half*32 + 8*u;
                #pragma unroll
                for (int jv = 0; jv < 8; jv++) {
                    unsigned b0 = Vt32[(8*jv + g)*VSTW + kpb + t4];
                    unsigned b1 = Vt32[(8*jv + g)*VSTW + kpb + t4 + 4];
                    mma16(oacc[0][jv], a00, a01, a02, a03, b0, b1);
                    mma16(oacc[1][jv], a10, a11, a12, a13, b0, b1);
                }
            }
        }
    }

    // ---- epilogue: normalized O + denominator d = l * 2^m ----
    float* Og = g_O + (long)(b*NW_ + wi)*M_*C_;
    float* Dg = g_D + (long)(b*NW_ + wi)*M_;
    #pragma unroll
    for (int mt = 0; mt < 2; mt++) {
        int r0_ = row0 + 16*mt + g, r1_ = r0_ + 8;
        float i0 = 1.0f / lrow[mt][0], i1 = 1.0f / lrow[mt][1];
        #pragma unroll
        for (int jv = 0; jv < 8; jv++) {
            *(float2*)&Og[(long)r0_*C_ + 8*jv + 2*t4] =
                make_float2(oacc[mt][jv][0]*i0, oacc[mt][jv][1]*i0);
            *(float2*)&Og[(long)r1_*C_ + 8*jv + 2*t4] =
                make_float2(oacc[mt][jv][2]*i1, oacc[mt][jv][3]*i1);
        }
        if (t4 == 0) {
            Dg[r0_] = lrow[mt][0] * ex2(mrow[mt][0]);
            Dg[r1_] = lrow[mt][1] * ex2(mrow[mt][1]);
        }
    }
}

// ============================ Kernel 3: mix ============================
__global__ __launch_bounds__(256) void mix_kernel(float* __restrict__ out) {
    const int tid = threadIdx.x;
    const int c = tid & 63;
    const int gp = blockIdx.x*4 + (tid >> 6);
    const int b = gp >> 13;
    const int p = gp & (N_-1);

    int w0 = p >> 11, r0 = p & 2047;
    long i0 = (long)(b*NW_ + w0)*M_ + r0;
    float d0 = g_D[i0];
    float dsum = d0;
    float num  = d0 * g_O[i0*C_ + c];

    if ((p & 1) == 0) {
        int w1 = 4 + (p >> 12), r1 = (p & 4095) >> 1;
        long i1 = (long)(b*NW_ + w1)*M_ + r1;
        float d1 = g_D[i1];
        dsum += d1;
        num  += d1 * g_O[i1*C_ + c];
    }
    if ((p & 3) == 0) {
        long i2 = (long)(b*NW_ + 6)*M_ + (p >> 2);
        float d2 = g_D[i2];
        dsum += d2;
        num  += d2 * g_O[i2*C_ + c];
    }
    out[((long)b*N_ + p)*C_ + c] = num / dsum;
}

// =======================================================================
extern "C" void kernel_launch(void* const* d_in, const int* in_sizes, int n_in,
                              void* d_out, int out_size) {
    (void)in_sizes; (void)n_in; (void)out_size;
    const float* x  = (const float*)d_in[0];
    const float* Wq = (const float*)d_in[1];
    const float* Wk = (const float*)d_in[2];
    const float* Wv = (const float*)d_in[3];
    float* out = (float*)d_out;

    const int smem1 = (64*64 + 64*192) * 4;            // 64 KB
    const int smem2 = (128*KST2 + 64*VSTW) * 4;        // 35840 B
    cudaFuncSetAttribute(qkv_kernel,  cudaFuncAttributeMaxDynamicSharedMemorySize, smem1);
    cudaFuncSetAttribute(attn_kernel, cudaFuncAttributeMaxDynamicSharedMemorySize, smem2);

    qkv_kernel<<<(B_*N_)/64, 256, smem1>>>(x, Wq, Wk, Wv);
    attn_kernel<<<NQB * B_ * NW_, 256, smem2>>>();
    mix_kernel<<<(B_*N_)/4, 256>>>(out);
}

// round 12
// speedup vs baseline: 1.6288x; 1.1582x over previous
#include <cuda_runtime.h>

#define B_  4
#define N_  8192
#define C_  64
#define M_  2048
#define NW_ 7
#define QB_ROWS 256
#define NQB 8
#define KST2 36          // K smem row stride in 32-bit words (fp16 c-pairs)
#define VSTW 68          // Vt row stride in 32-bit words (fp16 key-pairs)
#define WST2 36          // W^T smem row stride (fp16 k-pairs)
#define SCALE_LOG2 0.18033688011112042f  // (1/8) * log2(e)

// Q/K/V stored as packed fp16x2 words: [row][32 words], word w = channels (2w, 2w+1)
__device__ unsigned g_Qh[B_*N_*32];
__device__ unsigned g_Kh[B_*N_*32];
__device__ unsigned g_Vh[B_*N_*32];
__device__ float g_O[(long)B_*NW_*M_*C_];
__device__ float g_D[B_*NW_*M_];

__device__ __forceinline__ float ex2(float x) {
    float y; asm("ex2.approx.f32 %0, %1;" : "=f"(y) : "f"(x)); return y;
}
__device__ __forceinline__ void mma16(float d[4], unsigned a0, unsigned a1, unsigned a2,
                                      unsigned a3, unsigned b0, unsigned b1) {
    asm volatile("mma.sync.aligned.m16n8k16.row.col.f32.f16.f16.f32 "
        "{%0,%1,%2,%3},{%4,%5,%6,%7},{%8,%9},{%0,%1,%2,%3};"
        : "+f"(d[0]), "+f"(d[1]), "+f"(d[2]), "+f"(d[3])
        : "r"(a0), "r"(a1), "r"(a2), "r"(a3), "r"(b0), "r"(b1));
}
#define PACK2(D, HI, LO) asm("cvt.rn.f16x2.f32 %0, %1, %2;" : "=r"(D) : "f"(HI), "f"(LO))
#define PRMT(D, A, B, S) asm("prmt.b32 %0, %1, %2, %3;" : "=r"(D) : "r"(A), "r"(B), "n"(S))

// ============ Kernel 1: QKV projection — fp16 tensor cores, packed fp16 output ============
// grid 128 x 512 thr; CTA = 256 rows (2 iters of 128). Warp = (row-group, j-half);
// each warp: 16 rows x 12 n-tiles of 8.
__global__ __launch_bounds__(512) void qkv_kernel(const float* __restrict__ x,
                                                  const float* __restrict__ Wq,
                                                  const float* __restrict__ Wk,
                                                  const float* __restrict__ Wv) {
    extern __shared__ unsigned smw[];   // Wt16[192][WST2]
    const int tid = threadIdx.x;
    const int wid = tid >> 5, lane = tid & 31;
    const int g = lane >> 2, t4 = lane & 3;
    const int rw = wid >> 1;
    const int jh = (wid & 1) * 12;

    // stage W^T fp16: row n (out col), word w = in-channels (2w, 2w+1)
    const float* Wm[3] = {Wq, Wk, Wv};
    for (int idx = tid; idx < 192*32; idx += 512) {
        int nn = idx >> 5, w = idx & 31;
        const float* Wsrc = Wm[nn >> 6];
        float lo = Wsrc[(2*w    )*64 + (nn & 63)];
        float hi = Wsrc[(2*w + 1)*64 + (nn & 63)];
        unsigned pw; PACK2(pw, hi, lo);
        smw[nn*WST2 + w] = pw;
    }
    __syncthreads();

    #pragma unroll
    for (int it = 0; it < 2; it++) {
        const long row0 = (long)blockIdx.x*256 + it*128 + 16*rw;
        const float* x0 = x + (row0 + g)*C_;
        const float* x1 = x0 + 8*C_;
        unsigned a[4][4];
        #pragma unroll
        for (int kc = 0; kc < 4; kc++) {
            int k0 = 16*kc + 2*t4;
            PACK2(a[kc][0], x0[k0+1], x0[k0]);
            PACK2(a[kc][1], x1[k0+1], x1[k0]);
            PACK2(a[kc][2], x0[k0+9], x0[k0+8]);
            PACK2(a[kc][3], x1[k0+9], x1[k0+8]);
        }

        float acc[12][4];
        #pragma unroll
        for (int j = 0; j < 12; j++)
            #pragma unroll
            for (int q = 0; q < 4; q++) acc[j][q] = 0.f;

        #pragma unroll
        for (int kc = 0; kc < 4; kc++) {
            #pragma unroll
            for (int j = 0; j < 12; j++) {
                unsigned b0 = smw[(8*(jh + j) + g)*WST2 + 8*kc + t4];
                unsigned b1 = smw[(8*(jh + j) + g)*WST2 + 8*kc + t4 + 4];
                mma16(acc[j], a[kc][0], a[kc][1], a[kc][2], a[kc][3], b0, b1);
            }
        }

        const long r0 = row0 + g, r1 = r0 + 8;
        #pragma unroll
        for (int j = 0; j < 12; j++) {
            int jj = jh + j;
            unsigned* dst = (jj < 8) ? g_Qh : (jj < 16) ? g_Kh : g_Vh;
            float sc = (jj < 8) ? SCALE_LOG2 : 1.0f;
            int wd = 4*(jj & 7) + t4;
            unsigned w0, w1;
            PACK2(w0, acc[j][1]*sc, acc[j][0]*sc);
            PACK2(w1, acc[j][3]*sc, acc[j][2]*sc);
            dst[r0*32 + wd] = w0;
            dst[r1*32 + wd] = w1;
        }
    }
}

// ==== Kernel 2: flash attention — fp16 operands (fp32 accum), fp16 gmem, 128-key steps ====
__global__ __launch_bounds__(256, 1) void attn_kernel() {
    extern __shared__ unsigned smu[];
    unsigned* Ks16 = smu;                 // [128 key][KST2]
    unsigned* Vt32 = smu + 128*KST2;      // [64 c][VSTW]

    const int tid  = threadIdx.x;
    const int wid  = tid >> 5, lane = tid & 31;
    const int g    = lane >> 2, t4 = lane & 3;
    const int blk  = blockIdx.x;
    const int qb   = (NQB - 1) - blk / (B_*NW_);   // heaviest first (LPT)
    const int w    = blk % (B_*NW_);
    const int b    = w / NW_, wi = w % NW_;

    int base, r;
    if      (wi < 4) { base = wi*2048;     r = 1; }
    else if (wi < 6) { base = (wi-4)*4096; r = 2; }
    else             { base = 0;           r = 4; }

    const unsigned* Qg = g_Qh + ((long)b*N_ + base)*32;
    const unsigned* Kg = g_Kh + ((long)b*N_ + base)*32;
    const unsigned* Vg = g_Vh + ((long)b*N_ + base)*32;
    const int rsw = r * 32;               // row stride in words

    // ---- Q fragments: direct packed loads ----
    const int row0 = qb*QB_ROWS + 32*wid;
    unsigned qa[2][4][4];
    #pragma unroll
    for (int mt = 0; mt < 2; mt++) {
        const unsigned* q0 = Qg + (long)(row0 + 16*mt + g)*rsw;
        const unsigned* q1 = q0 + (long)8*rsw;
        #pragma unroll
        for (int kc = 0; kc < 4; kc++) {
            qa[mt][kc][0] = q0[8*kc + t4];
            qa[mt][kc][1] = q1[8*kc + t4];
            qa[mt][kc][2] = q0[8*kc + t4 + 4];
            qa[mt][kc][3] = q1[8*kc + t4 + 4];
        }
    }

    float oacc[2][8][4];
    float mrow[2][2], lrow[2][2];
    #pragma unroll
    for (int mt = 0; mt < 2; mt++) {
        mrow[mt][0] = mrow[mt][1] = -1e30f;
        lrow[mt][0] = lrow[mt][1] = 0.f;
        #pragma unroll
        for (int j = 0; j < 8; j++)
            #pragma unroll
            for (int q = 0; q < 4; q++) oacc[mt][j][q] = 0.f;
    }

    const int nks = 2*qb + 2;          // 128-key steps
    for (int ks = 0; ks < nks; ks++) {
        __syncthreads();
        // ---- fill K: raw packed copy, 128 rows x 32 words ----
        #pragma unroll
        for (int i = 0; i < 4; i++) {
            int l = tid + i*256;
            int slot = l >> 3, wg = (l & 7) << 2;
            uint4 kw = *(const uint4*)(Kg + (long)(ks*128 + slot)*rsw + wg);
            *(uint4*)&Ks16[slot*KST2 + wg] = kw;
        }
        // ---- fill V transposed: Vt[c][keypair] via prmt ----
        #pragma unroll
        for (int i = 0; i < 4; i++) {
            int l = tid + i*256;
            int kp = ((l >> 7) << 3) | (l & 7);    // keypair 0..63
            int cw = (l >> 3) & 15;                // channel-word pair base
            const unsigned* va = Vg + (long)(ks*128 + 2*kp)*rsw + 2*cw;
            uint2 a2 = *(const uint2*)va;
            uint2 b2 = *(const uint2*)(va + rsw);
            unsigned p0, p1, p2, p3;
            PRMT(p0, a2.x, b2.x, 0x5410);
            PRMT(p1, a2.x, b2.x, 0x7632);
            PRMT(p2, a2.y, b2.y, 0x5410);
            PRMT(p3, a2.y, b2.y, 0x7632);
            Vt32[(4*cw+0)*VSTW + kp] = p0;
            Vt32[(4*cw+1)*VSTW + kp] = p1;
            Vt32[(4*cw+2)*VSTW + kp] = p2;
            Vt32[(4*cw+3)*VSTW + kp] = p3;
        }
        __syncthreads();

        #pragma unroll
        for (int half = 0; half < 2; half++) {
            const int kbase = ks*128 + half*64;

            // ---- S = Q K^T (fp16 k16) ----
            float sacc[2][8][4];
            #pragma unroll
            for (int mt = 0; mt < 2; mt++)
                #pragma unroll
                for (int j = 0; j < 8; j++)
                    #pragma unroll
                    for (int q = 0; q < 4; q++) sacc[mt][j][q] = 0.f;

            #pragma unroll
            for (int kc = 0; kc < 4; kc++) {
                #pragma unroll
                for (int j = 0; j < 8; j++) {
                    const unsigned* kr = Ks16 + (half*64 + 8*j + g)*KST2 + 8*kc + t4;
                    unsigned b0 = kr[0];
                    unsigned b1 = kr[4];
                    mma16(sacc[0][j], qa[0][kc][0], qa[0][kc][1], qa[0][kc][2], qa[0][kc][3], b0, b1);
                    mma16(sacc[1][j], qa[1][kc][0], qa[1][kc][1], qa[1][kc][2], qa[1][kc][3], b0, b1);
                }
            }

            // ---- causal mask (C cols: 8j+2t4, 8j+2t4+1) ----
            if (ks >= 2*qb) {
                #pragma unroll
                for (int mt = 0; mt < 2; mt++) {
                    int r0_ = row0 + 16*mt + g, r1_ = r0_ + 8;
                    #pragma unroll
                    for (int j = 0; j < 8; j++) {
                        int k0 = kbase + 8*j + 2*t4, k1 = k0 + 1;
                        if (k0 > r0_) sacc[mt][j][0] = -1e30f;
                        if (k1 > r0_) sacc[mt][j][1] = -1e30f;
                        if (k0 > r1_) sacc[mt][j][2] = -1e30f;
                        if (k1 > r1_) sacc[mt][j][3] = -1e30f;
                    }
                }
            }

            // ---- online softmax (log2 domain) ----
            #pragma unroll
            for (int mt = 0; mt < 2; mt++) {
                float rm0 = -1e30f, rm1 = -1e30f;
                #pragma unroll
                for (int j = 0; j < 8; j++) {
                    rm0 = fmaxf(rm0, fmaxf(sacc[mt][j][0], sacc[mt][j][1]));
                    rm1 = fmaxf(rm1, fmaxf(sacc[mt][j][2], sacc[mt][j][3]));
                }
                rm0 = fmaxf(rm0, __shfl_xor_sync(0xffffffffu, rm0, 1));
                rm0 = fmaxf(rm0, __shfl_xor_sync(0xffffffffu, rm0, 2));
                rm1 = fmaxf(rm1, __shfl_xor_sync(0xffffffffu, rm1, 1));
                rm1 = fmaxf(rm1, __shfl_xor_sync(0xffffffffu, rm1, 2));
                float mn0 = fmaxf(mrow[mt][0], rm0), mn1 = fmaxf(mrow[mt][1], rm1);
                float c0 = ex2(mrow[mt][0] - mn0),   c1 = ex2(mrow[mt][1] - mn1);
                mrow[mt][0] = mn0; mrow[mt][1] = mn1;
                float rs0 = 0.f, rs1 = 0.f;
                #pragma unroll
                for (int j = 0; j < 8; j++) {
                    float p0 = ex2(sacc[mt][j][0] - mn0); rs0 += p0; sacc[mt][j][0] = p0;
                    float p1 = ex2(sacc[mt][j][1] - mn0); rs0 += p1; sacc[mt][j][1] = p1;
                    float p2 = ex2(sacc[mt][j][2] - mn1); rs1 += p2; sacc[mt][j][2] = p2;
                    float p3 = ex2(sacc[mt][j][3] - mn1); rs1 += p3; sacc[mt][j][3] = p3;
                }
                rs0 += __shfl_xor_sync(0xffffffffu, rs0, 1);
                rs0 += __shfl_xor_sync(0xffffffffu, rs0, 2);
                rs1 += __shfl_xor_sync(0xffffffffu, rs1, 1);
                rs1 += __shfl_xor_sync(0xffffffffu, rs1, 2);
                lrow[mt][0] = lrow[mt][0]*c0 + rs0;
                lrow[mt][1] = lrow[mt][1]*c1 + rs1;
                #pragma unroll
                for (int jv = 0; jv < 8; jv++) {
                    oacc[mt][jv][0] *= c0; oacc[mt][jv][1] *= c0;
                    oacc[mt][jv][2] *= c1; oacc[mt][jv][3] *= c1;
                }
            }

            // ---- O += P V ----
            #pragma unroll
            for (int u = 0; u < 4; u++) {
                unsigned a00, a01, a02, a03, a10, a11, a12, a13;
                PACK2(a00, sacc[0][2*u  ][1], sacc[0][2*u  ][0]);
                PACK2(a01, sacc[0][2*u  ][3], sacc[0][2*u  ][2]);
                PACK2(a02, sacc[0][2*u+1][1], sacc[0][2*u+1][0]);
                PACK2(a03, sacc[0][2*u+1][3], sacc[0][2*u+1][2]);
                PACK2(a10, sacc[1][2*u  ][1], sacc[1][2*u  ][0]);
                PACK2(a11, sacc[1][2*u  ][3], sacc[1][2*u  ][2]);
                PACK2(a12, sacc[1][2*u+1][1], sacc[1][2*u+1][0]);
                PACK2(a13, sacc[1][2*u+1][3], sacc[1][2*u+1][2]);
                const int kpb = half*32 + 8*u;
                #pragma unroll
                for (int jv = 0; jv < 8; jv++) {
                    unsigned b0 = Vt32[(8*jv + g)*VSTW + kpb + t4];
                    unsigned b1 = Vt32[(8*jv + g)*VSTW + kpb + t4 + 4];
                    mma16(oacc[0][jv], a00, a01, a02, a03, b0, b1);
                    mma16(oacc[1][jv], a10, a11, a12, a13, b0, b1);
                }
            }
        }
    }

    // ---- epilogue: normalized O + denominator d = l * 2^m ----
    float* Og = g_O + (long)(b*NW_ + wi)*M_*C_;
    float* Dg = g_D + (long)(b*NW_ + wi)*M_;
    #pragma unroll
    for (int mt = 0; mt < 2; mt++) {
        int r0_ = row0 + 16*mt + g, r1_ = r0_ + 8;
        float i0 = 1.0f / lrow[mt][0], i1 = 1.0f / lrow[mt][1];
        #pragma unroll
        for (int jv = 0; jv < 8; jv++) {
            *(float2*)&Og[(long)r0_*C_ + 8*jv + 2*t4] =
                make_float2(oacc[mt][jv][0]*i0, oacc[mt][jv][1]*i0);
            *(float2*)&Og[(long)r1_*C_ + 8*jv + 2*t4] =
                make_float2(oacc[mt][jv][2]*i1, oacc[mt][jv][3]*i1);
        }
        if (t4 == 0) {
            Dg[r0_] = lrow[mt][0] * ex2(mrow[mt][0]);
            Dg[r1_] = lrow[mt][1] * ex2(mrow[mt][1]);
        }
    }
}

// ============================ Kernel 3: mix ============================
__global__ __launch_bounds__(256) void mix_kernel(float* __restrict__ out) {
    const int tid = threadIdx.x;
    const int c = tid & 63;
    const int gp = blockIdx.x*4 + (tid >> 6);
    const int b = gp >> 13;
    const int p = gp & (N_-1);

    int w0 = p >> 11, r0 = p & 2047;
    long i0 = (long)(b*NW_ + w0)*M_ + r0;
    float d0 = g_D[i0];
    float dsum = d0;
    float num  = d0 * g_O[i0*C_ + c];

    if ((p & 1) == 0) {
        int w1 = 4 + (p >> 12), r1 = (p & 4095) >> 1;
        long i1 = (long)(b*NW_ + w1)*M_ + r1;
        float d1 = g_D[i1];
        dsum += d1;
        num  += d1 * g_O[i1*C_ + c];
    }
    if ((p & 3) == 0) {
        long i2 = (long)(b*NW_ + 6)*M_ + (p >> 2);
        float d2 = g_D[i2];
        dsum += d2;
        num  += d2 * g_O[i2*C_ + c];
    }
    out[((long)b*N_ + p)*C_ + c] = num / dsum;
}

// =======================================================================
extern "C" void kernel_launch(void* const* d_in, const int* in_sizes, int n_in,
                              void* d_out, int out_size) {
    (void)in_sizes; (void)n_in; (void)out_size;
    const float* x  = (const float*)d_in[0];
    const float* Wq = (const float*)d_in[1];
    const float* Wk = (const float*)d_in[2];
    const float* Wv = (const float*)d_in[3];
    float* out = (float*)d_out;

    const int smem1 = 192*WST2*4;                      // 27648 B
    const int smem2 = (128*KST2 + 64*VSTW) * 4;        // 35840 B
    cudaFuncSetAttribute(qkv_kernel,  cudaFuncAttributeMaxDynamicSharedMemorySize, smem1);
    cudaFuncSetAttribute(attn_kernel, cudaFuncAttributeMaxDynamicSharedMemorySize, smem2);

    qkv_kernel<<<(B_*N_)/256, 512, smem1>>>(x, Wq, Wk, Wv);
    attn_kernel<<<NQB * B_ * NW_, 256, smem2>>>();
    mix_kernel<<<(B_*N_)/4, 256>>>(out);
}